// round 14
// baseline (speedup 1.0000x reference)
#include <cuda_runtime.h>
#include <cuda_fp16.h>
#include <cstdint>

#define B_   2
#define S_   2048
#define E_   1024
#define H_   16
#define DH_  64
#define FF_  4096
#define TOK  (B_*S_)   // 4096
#define NQKV 3072

// ---------------- scratch (no allocs allowed) ----------------
__device__ __half g_nx   [TOK*(size_t)E_];
__device__ __half g_wqkv [(size_t)NQKV*E_];
__device__ __half g_wo   [(size_t)E_*E_];
__device__ __half g_w1   [(size_t)FF_*E_];
__device__ __half g_w2   [(size_t)E_*FF_];
__device__ __half g_q [(size_t)B_*H_*S_*DH_];
__device__ __half g_k [(size_t)B_*H_*S_*DH_];
__device__ __half g_vt[(size_t)B_*H_*DH_*S_];   // V transposed: [B,H,DH,S]
__device__ __half g_attn[TOK*(size_t)E_];
__device__ float g_x1[TOK*(size_t)E_];
__device__ __half g_nx2 [TOK*(size_t)E_];
__device__ __half g_ffn [TOK*(size_t)FF_];

// ---------------- PTX helpers (base-target-safe: sm_80 features) -------------
__device__ __forceinline__ uint32_t smem_u32(const void* p) {
    uint32_t a;
    asm("{ .reg .u64 t; cvta.to.shared.u64 t, %1; cvt.u32.u64 %0, t; }" : "=r"(a) : "l"(p));
    return a;
}
__device__ __forceinline__ uint32_t h2_as_u32(__half2 h) {
    union { __half2 h2; uint32_t u; } cvt;
    cvt.h2 = h;
    return cvt.u;
}
__device__ __forceinline__ void cp16(uint32_t s, const void* g) {
    asm volatile("cp.async.cg.shared.global [%0], [%1], 16;" :: "r"(s), "l"(g));
}
#define CP_COMMIT() asm volatile("cp.async.commit_group;" ::: "memory")
#define CP_WAIT(n)  asm volatile("cp.async.wait_group %0;" :: "n"(n) : "memory")

__device__ __forceinline__ void ldm_x4(uint32_t& r0, uint32_t& r1, uint32_t& r2,
                                       uint32_t& r3, uint32_t a) {
    asm volatile("ldmatrix.sync.aligned.m8n8.x4.shared.b16 {%0,%1,%2,%3}, [%4];"
                 : "=r"(r0), "=r"(r1), "=r"(r2), "=r"(r3) : "r"(a));
}
__device__ __forceinline__ void mma16816(float* c, uint32_t a0, uint32_t a1,
                                         uint32_t a2, uint32_t a3,
                                         uint32_t b0, uint32_t b1) {
    asm volatile(
        "mma.sync.aligned.m16n8k16.row.col.f32.f16.f16.f32 "
        "{%0,%1,%2,%3},{%4,%5,%6,%7},{%8,%9},{%0,%1,%2,%3};"
        : "+f"(c[0]), "+f"(c[1]), "+f"(c[2]), "+f"(c[3])
        : "r"(a0), "r"(a1), "r"(a2), "r"(a3), "r"(b0), "r"(b1));
}

// fast 2^x on the FMA pipe (no MUFU). x clamped to [-125, ~0]. rel err ~1e-7.
__device__ __forceinline__ float fexp2(float x) {
    x = fmaxf(x, -125.0f);
    float t = x + 12582912.0f;              // 1.5*2^23: round-to-int in mantissa
    int n = __float_as_int(t) - 0x4B400000; // integer part
    float f = x - (t - 12582912.0f);        // frac in [-0.5, 0.5]
    float p =              1.5403530e-4f;
    p = fmaf(p, f, 1.3333558e-3f);
    p = fmaf(p, f, 9.6181291e-3f);
    p = fmaf(p, f, 5.5504109e-2f);
    p = fmaf(p, f, 2.4022651e-1f);
    p = fmaf(p, f, 6.9314718e-1f);
    p = fmaf(p, f, 1.0f);
    return p * __int_as_float((n + 127) << 23);
}

// ---------------- LayerNorm -> fp16: one block per token ---------------------
__global__ void __launch_bounds__(256) ln_fp16_kernel(
    const float* __restrict__ x, const float* __restrict__ g,
    const float* __restrict__ bta, __half* __restrict__ o)
{
    __shared__ float sh1[8], sh2[8];
    int tok = blockIdx.x;
    int t = threadIdx.x;
    const float4* xr = (const float4*)(x + (size_t)tok * E_);
    float4 v = xr[t];
    float sum = v.x + v.y + v.z + v.w;
    float sq  = v.x*v.x + v.y*v.y + v.z*v.z + v.w*v.w;
    #pragma unroll
    for (int o2 = 16; o2 > 0; o2 >>= 1) {
        sum += __shfl_xor_sync(0xffffffffu, sum, o2);
        sq  += __shfl_xor_sync(0xffffffffu, sq,  o2);
    }
    if ((t & 31) == 0) { sh1[t >> 5] = sum; sh2[t >> 5] = sq; }
    __syncthreads();
    if (t < 32) {
        sum = (t < 8) ? sh1[t] : 0.f;
        sq  = (t < 8) ? sh2[t] : 0.f;
        #pragma unroll
        for (int o2 = 4; o2 > 0; o2 >>= 1) {
            sum += __shfl_xor_sync(0xffffffffu, sum, o2);
            sq  += __shfl_xor_sync(0xffffffffu, sq,  o2);
        }
        if (t == 0) { sh1[0] = sum; sh2[0] = sq; }
    }
    __syncthreads();
    sum = sh1[0]; sq = sh2[0];
    float mu  = sum * (1.0f / E_);
    float var = sq * (1.0f / E_) - mu * mu;
    float rs  = rsqrtf(var + 1e-5f);
    float4 gv = ((const float4*)g)[t];
    float4 bv = ((const float4*)bta)[t];
    float a0 = (v.x - mu) * rs * gv.x + bv.x;
    float a1 = (v.y - mu) * rs * gv.y + bv.y;
    float a2 = (v.z - mu) * rs * gv.z + bv.z;
    float a3 = (v.w - mu) * rs * gv.w + bv.w;
    size_t base = (size_t)tok * E_ + t * 4;
    *(__half2*)(o + base)     = __floats2half2_rn(a0, a1);
    *(__half2*)(o + base + 2) = __floats2half2_rn(a2, a3);
}

// ---------------- weight transpose -> fp16: W[K,N] -> Wt[N,K] ----------------
__global__ void __launch_bounds__(256) wt_fp16_kernel(
    const float* __restrict__ W, int K, int N, __half* __restrict__ o)
{
    __shared__ float t[32][33];
    int k0 = blockIdx.x * 32, n0 = blockIdx.y * 32;
    int tx = threadIdx.x & 31, ty = threadIdx.x >> 5;
    #pragma unroll
    for (int r = 0; r < 4; r++)
        t[ty + 8*r][tx] = W[(size_t)(k0 + ty + 8*r) * N + n0 + tx];
    __syncthreads();
    #pragma unroll
    for (int r = 0; r < 4; r++)
        o[(size_t)(n0 + ty + 8*r) * K + k0 + tx] = __float2half_rn(t[tx][ty + 8*r]);
}

// QKV weights [H,E,DH] x3 -> fused Wt[3072, E] fp16
__global__ void __launch_bounds__(256) wqkv_fp16_kernel(
    const float* __restrict__ Wq, const float* __restrict__ Wk,
    const float* __restrict__ Wv, __half* __restrict__ o)
{
    __shared__ float t[32][33];
    int e0 = blockIdx.x * 32, n0 = blockIdx.y * 32;
    const float* Wm = (n0 < 1024) ? Wq : (n0 < 2048) ? Wk : Wv;
    int nn = n0 & 1023;
    int h = nn >> 6, d0 = nn & 63;
    int tx = threadIdx.x & 31, ty = threadIdx.x >> 5;
    #pragma unroll
    for (int r = 0; r < 4; r++)
        t[ty + 8*r][tx] = Wm[((size_t)h * E_ + e0 + ty + 8*r) * DH_ + d0 + tx];
    __syncthreads();
    #pragma unroll
    for (int r = 0; r < 4; r++)
        o[(size_t)(n0 + ty + 8*r) * E_ + e0 + tx] = __float2half_rn(t[tx][ty + 8*r]);
}

// ---------------- HMMA GEMM: C[M,N] = A[M,K]*Bt[N,K]^T, plain fp16 -----------
// 128 threads, 4 warps, each warp 64x64. BK=64, 3 stages, prefetch distance 2:
//   group G_j = load of chunk j (or empty commit past the tail).
//   at iter i: CP_WAIT(1) -> G_i complete (chunk i resident); sync retires slot
//   (i-1)%3; prefetch chunk i+2 into slot (i+2)%3 == (i-1)%3 (now safe).
#define BK     64
#define GLDS   72
#define ABYTES (128 * GLDS * 2)        // 18432
#define STG_BYTES (2 * ABYTES)         // 36864
#define GEMM_SMEM (3 * STG_BYTES)      // 110592 -> 2 CTA/SM

template<int MODE>
__global__ void __launch_bounds__(128, 2) gemm_mma_kernel(
    const __half* __restrict__ A, const __half* __restrict__ Bt,
    const float* __restrict__ bias, const float* __restrict__ res,
    float* __restrict__ o0, __half* __restrict__ oh,
    __half* __restrict__ q16, __half* __restrict__ k16, __half* __restrict__ v16,
    int K, int ldC)
{
    extern __shared__ __half smbuf[];
    const uint32_t sbase = smem_u32(smbuf);
    const int NIT = K / BK;
    const int t = threadIdx.x;
    const int wid = t >> 5, lane = t & 31;
    const int bm = blockIdx.y * 128, bn = blockIdx.x * 128;
    const int wm = (wid & 1) * 64, wn = (wid >> 1) * 64;

    const __half* Abase = A  + (size_t)bm * K;
    const __half* Bbase = Bt + (size_t)bn * K;

    auto load_stage = [&](int st, int i) {
        uint32_t sa = sbase + st * STG_BYTES;
        int kc = i * BK;
        #pragma unroll
        for (int p = 0; p < 8; p++) {
            int idx = t + p * 128;
            int row = idx >> 3, ch = idx & 7;
            uint32_t off = (uint32_t)(row * GLDS + ch * 8) * 2;
            cp16(sa + off,          Abase + (size_t)row * K + kc + ch * 8);
            cp16(sa + ABYTES + off, Bbase + (size_t)row * K + kc + ch * 8);
        }
    };

    // prologue: chunks 0,1 into slots 0,1 (one commit group each)
    load_stage(0, 0); CP_COMMIT();
    load_stage(1, 1); CP_COMMIT();

    float c[4][8][4];
    #pragma unroll
    for (int mt = 0; mt < 4; mt++)
        #pragma unroll
        for (int nt = 0; nt < 8; nt++)
            #pragma unroll
            for (int e = 0; e < 4; e++) c[mt][nt][e] = 0.f;

    int stage = 0;          // = i % 3
    int pf    = 2;          // prefetch slot = (i+2) % 3
    for (int i = 0; i < NIT; i++) {
        CP_WAIT(1);         // all but newest group done -> chunk i resident
        __syncthreads();
        if (i + 2 < NIT) load_stage(pf, i + 2);
        CP_COMMIT();        // unconditional: keeps group count aligned at tail

        uint32_t sa = sbase + stage * STG_BYTES;
        uint32_t sb = sa + ABYTES;
        #pragma unroll
        for (int ks = 0; ks < 4; ks++) {
            uint32_t a[4][4];
            #pragma unroll
            for (int mt = 0; mt < 4; mt++) {
                uint32_t addr = sa + (uint32_t)(((wm + mt*16 + (lane & 15)) * GLDS
                                  + ks*16 + (lane >> 4) * 8) * 2);
                ldm_x4(a[mt][0], a[mt][1], a[mt][2], a[mt][3], addr);
            }
            uint32_t b[8][2];
            #pragma unroll
            for (int np = 0; np < 4; np++) {
                int nrow = wn + np*16 + (lane & 7) + ((lane >> 4) << 3);
                int ncol = ks*16 + (((lane >> 3) & 1) << 3);
                uint32_t addr = sb + (uint32_t)((nrow * GLDS + ncol) * 2);
                uint32_t r0, r1, r2, r3;
                ldm_x4(r0, r1, r2, r3, addr);
                b[2*np][0] = r0; b[2*np][1] = r1;
                b[2*np+1][0] = r2; b[2*np+1][1] = r3;
            }
            #pragma unroll
            for (int mt = 0; mt < 4; mt++)
                #pragma unroll
                for (int nt = 0; nt < 8; nt++)
                    mma16816(c[mt][nt], a[mt][0], a[mt][1], a[mt][2], a[mt][3],
                             b[nt][0], b[nt][1]);
        }
        stage = (stage == 2) ? 0 : stage + 1;
        pf    = (pf    == 2) ? 0 : pf    + 1;
    }

    // ---------------- epilogue ----------------
    const int r = lane >> 2, cq = (lane & 3) * 2;
    #pragma unroll
    for (int mt = 0; mt < 4; mt++) {
        #pragma unroll
        for (int half_ = 0; half_ < 2; half_++) {
            int m = bm + wm + mt * 16 + r + half_ * 8;
            #pragma unroll
            for (int nt = 0; nt < 8; nt++) {
                int n = bn + wn + nt * 8 + cq;
                float v0 = c[mt][nt][half_ * 2 + 0];
                float v1 = c[mt][nt][half_ * 2 + 1];
                if (MODE == 0) {
                    int mat = n >> 10;
                    int hh = (n & 1023) >> 6, d = n & 63;
                    int bb = m >> 11, srow = m & (S_ - 1);
                    if (mat < 2) {
                        __half* dst = (mat == 0) ? q16 : k16;
                        *(__half2*)(dst + (((size_t)(bb * H_ + hh) * S_ + srow) << 6) + d)
                            = __floats2half2_rn(v0, v1);
                    } else {
                        __half* p = v16 + ((size_t)(bb * H_ + hh) * DH_ + d) * S_ + srow;
                        p[0]  = __float2half_rn(v0);
                        p[S_] = __float2half_rn(v1);
                    }
                } else if (MODE == 2) {
                    float2 bv = *(const float2*)(bias + n);
                    v0 = fmaxf(v0 + bv.x, 0.f);
                    v1 = fmaxf(v1 + bv.y, 0.f);
                    *(__half2*)(oh + (size_t)m * ldC + n) = __floats2half2_rn(v0, v1);
                } else {
                    size_t base = (size_t)m * ldC + n;
                    float2 bv = *(const float2*)(bias + n);
                    float2 rv = *(const float2*)(res + base);
                    *(float2*)(o0 + base) = make_float2(v0 + bv.x + rv.x,
                                                        v1 + bv.y + rv.y);
                }
            }
        }
    }
}

// ---------------- HMMA flash attention (causal) -------------------------------
// 128 queries x 64 keys per tile, 4 warps (32 q-rows each), fp16 in, fp16 out.
// (R10 structure: fragment loads inline per ks — proven fastest, no spills)
#define FLDS 72
#define FLASH_SMEM ((128 + 4*64) * FLDS * 2)   // 55296 B

__global__ void __launch_bounds__(128, 2) flash_kernel(
    const __half* __restrict__ Q, const __half* __restrict__ Kp,
    const __half* __restrict__ Vt, __half* __restrict__ O)
{
    extern __shared__ __half fsm[];
    const uint32_t qb = smem_u32(fsm);                 // Q [128][72]
    const uint32_t kb = qb + 128 * FLDS * 2;           // K [2][64][72]
    const uint32_t vb = kb + 2 * 64 * FLDS * 2;        // Vt [2][64][72]

    const int qt = (int)gridDim.x - 1 - (int)blockIdx.x;   // heavy tiles first
    const int h = blockIdx.y, b = blockIdx.z;
    const int t = threadIdx.x, wid = t >> 5, lane = t & 31;
    const int wm = wid * 32;

    const __half* Qg = Q  + (((size_t)(b * H_ + h)) * S_ + qt * 128) * DH_;
    const __half* Kg = Kp + ((size_t)(b * H_ + h)) * S_ * DH_;
    const __half* Vg = Vt + ((size_t)(b * H_ + h)) * DH_ * S_;

    auto load_kv = [&](int kt) {
        uint32_t st = (uint32_t)(kt & 1) * 64 * FLDS * 2;
        #pragma unroll
        for (int p = 0; p < 4; p++) {
            int idx = t + p * 128;
            int row = idx >> 3, ch = idx & 7;
            uint32_t off = (uint32_t)(row * FLDS + ch * 8) * 2;
            cp16(kb + st + off, Kg + (size_t)(kt * 64 + row) * DH_ + ch * 8);
            cp16(vb + st + off, Vg + (size_t)row * S_ + kt * 64 + ch * 8);
        }
    };

    // Q + KV(0) in one group
    #pragma unroll
    for (int p = 0; p < 8; p++) {
        int idx = t + p * 128;
        int row = idx >> 3, ch = idx & 7;
        cp16(qb + (uint32_t)(row * FLDS + ch * 8) * 2, Qg + (size_t)row * DH_ + ch * 8);
    }
    load_kv(0);
    CP_COMMIT();

    const float alpha = 0.125f * 1.44269504f;   // scale * log2(e)
    float mrow[2][2], lrow[2][2];
    #pragma unroll
    for (int mt = 0; mt < 2; mt++) {
        mrow[mt][0] = -1e30f; mrow[mt][1] = -1e30f;
        lrow[mt][0] = 0.f;    lrow[mt][1] = 0.f;
    }
    float oc[2][8][4];
    #pragma unroll
    for (int mt = 0; mt < 2; mt++)
        #pragma unroll
        for (int j = 0; j < 8; j++)
            #pragma unroll
            for (int e = 0; e < 4; e++) oc[mt][j][e] = 0.f;

    uint32_t qa[2][4][4];
    const int nkt = 2 * qt + 2;

    for (int kt = 0; kt < nkt; kt++) {
        if (kt + 1 < nkt) { load_kv(kt + 1); CP_COMMIT(); CP_WAIT(1); }
        else              { CP_WAIT(0); }
        __syncthreads();

        if (kt == 0) {   // Q fragments, loaded once
            #pragma unroll
            for (int mt = 0; mt < 2; mt++)
                #pragma unroll
                for (int ks = 0; ks < 4; ks++) {
                    uint32_t addr = qb + (uint32_t)(((wm + mt*16 + (lane & 15)) * FLDS
                                       + ks * 16 + (lane >> 4) * 8) * 2);
                    ldm_x4(qa[mt][ks][0], qa[mt][ks][1], qa[mt][ks][2], qa[mt][ks][3], addr);
                }
        }

        // ---- S = Q K^T ----
        float sc[2][8][4];
        #pragma unroll
        for (int mt = 0; mt < 2; mt++)
            #pragma unroll
            for (int j = 0; j < 8; j++)
                #pragma unroll
                for (int e = 0; e < 4; e++) sc[mt][j][e] = 0.f;

        uint32_t kbs = kb + (uint32_t)(kt & 1) * 64 * FLDS * 2;
        #pragma unroll
        for (int ks = 0; ks < 4; ks++) {
            uint32_t bfr[8][2];
            #pragma unroll
            for (int np = 0; np < 4; np++) {
                int nrow = np * 16 + (lane & 7) + ((lane >> 4) << 3);
                int ncol = ks * 16 + (((lane >> 3) & 1) << 3);
                uint32_t r0, r1, r2, r3;
                ldm_x4(r0, r1, r2, r3, kbs + (uint32_t)((nrow * FLDS + ncol) * 2));
                bfr[2*np][0] = r0; bfr[2*np][1] = r1;
                bfr[2*np+1][0] = r2; bfr[2*np+1][1] = r3;
            }
            #pragma unroll
            for (int mt = 0; mt < 2; mt++)
                #pragma unroll
                for (int j = 0; j < 8; j++)
                    mma16816(sc[mt][j], qa[mt][ks][0], qa[mt][ks][1],
                             qa[mt][ks][2], qa[mt][ks][3], bfr[j][0], bfr[j][1]);
        }

        // ---- causal mask (only diagonal key tiles) ----
        if (kt >= 2 * qt) {
            #pragma unroll
            for (int mt = 0; mt < 2; mt++) {
                int row0 = qt * 128 + wm + mt * 16 + (lane >> 2);
                int colb = kt * 64 + 2 * (lane & 3);
                #pragma unroll
                for (int j = 0; j < 8; j++) {
                    #pragma unroll
                    for (int cc = 0; cc < 2; cc++) {
                        int col = colb + j * 8 + cc;
                        if (col > row0)     sc[mt][j][cc]     = -1e30f;
                        if (col > row0 + 8) sc[mt][j][2 + cc] = -1e30f;
                    }
                }
            }
        }

        // ---- online softmax + P packing ----
        uint32_t pa[2][4][4];
        float corr[2][2];
        #pragma unroll
        for (int mt = 0; mt < 2; mt++) {
            float mx0 = -1e30f, mx1 = -1e30f;
            #pragma unroll
            for (int j = 0; j < 8; j++) {
                mx0 = fmaxf(mx0, fmaxf(sc[mt][j][0], sc[mt][j][1]));
                mx1 = fmaxf(mx1, fmaxf(sc[mt][j][2], sc[mt][j][3]));
            }
            mx0 = fmaxf(mx0, __shfl_xor_sync(0xffffffffu, mx0, 1));
            mx0 = fmaxf(mx0, __shfl_xor_sync(0xffffffffu, mx0, 2));
            mx1 = fmaxf(mx1, __shfl_xor_sync(0xffffffffu, mx1, 1));
            mx1 = fmaxf(mx1, __shfl_xor_sync(0xffffffffu, mx1, 2));
            float nm0 = fmaxf(mrow[mt][0], mx0), nm1 = fmaxf(mrow[mt][1], mx1);
            corr[mt][0] = fexp2((mrow[mt][0] - nm0) * alpha);
            corr[mt][1] = fexp2((mrow[mt][1] - nm1) * alpha);
            mrow[mt][0] = nm0; mrow[mt][1] = nm1;
            float ma0 = nm0 * alpha, ma1 = nm1 * alpha;

            float rs0 = 0.f, rs1 = 0.f;
            #pragma unroll
            for (int j = 0; j < 8; j++) {
                float p0 = fexp2(fmaf(sc[mt][j][0], alpha, -ma0));
                float p1 = fexp2(fmaf(sc[mt][j][1], alpha, -ma0));
                float p2 = fexp2(fmaf(sc[mt][j][2], alpha, -ma1));
                float p3 = fexp2(fmaf(sc[mt][j][3], alpha, -ma1));
                rs0 += p0 + p1; rs1 += p2 + p3;
                int ks = j >> 1, hi = (j & 1) << 1;
                pa[mt][ks][hi]     = h2_as_u32(__floats2half2_rn(p0, p1));
                pa[mt][ks][hi + 1] = h2_as_u32(__floats2half2_rn(p2, p3));
            }
            rs0 += __shfl_xor_sync(0xffffffffu, rs0, 1);
            rs0 += __shfl_xor_sync(0xffffffffu, rs0, 2);
            rs1 += __shfl_xor_sync(0xffffffffu, rs1, 1);
            rs1 += __shfl_xor_sync(0xffffffffu, rs1, 2);
            lrow[mt][0] = lrow[mt][0] * corr[mt][0] + rs0;
            lrow[mt][1] = lrow[mt][1] * corr[mt][1] + rs1;
            #pragma unroll
            for (int j = 0; j < 8; j++) {
                oc[mt][j][0] *= corr[mt][0]; oc[mt][j][1] *= corr[mt][0];
                oc[mt][j][2] *= corr[mt][1]; oc[mt][j][3] *= corr[mt][1];
            }
        }

        // ---- O += P V ----
        uint32_t vbs = vb + (uint32_t)(kt & 1) * 64 * FLDS * 2;
        #pragma unroll
        for (int ks = 0; ks < 4; ks++) {
            uint32_t vfr[8][2];
            #pragma unroll
            for (int np = 0; np < 4; np++) {
                int nrow = np * 16 + (lane & 7) + ((lane >> 4) << 3);
                int ncol = ks * 16 + (((lane >> 3) & 1) << 3);
                uint32_t r0, r1, r2, r3;
                ldm_x4(r0, r1, r2, r3, vbs + (uint32_t)((nrow * FLDS + ncol) * 2));
                vfr[2*np][0] = r0; vfr[2*np][1] = r1;
                vfr[2*np+1][0] = r2; vfr[2*np+1][1] = r3;
            }
            #pragma unroll
            for (int mt = 0; mt < 2; mt++)
                #pragma unroll
                for (int j = 0; j < 8; j++)
                    mma16816(oc[mt][j], pa[mt][ks][0], pa[mt][ks][1],
                             pa[mt][ks][2], pa[mt][ks][3], vfr[j][0], vfr[j][1]);
        }
        __syncthreads();
    }

    // ---- write O (concat layout, fp16) ----
    #pragma unroll
    for (int mt = 0; mt < 2; mt++) {
        float i0 = 1.0f / lrow[mt][0], i1 = 1.0f / lrow[mt][1];
        int row0 = qt * 128 + wm + mt * 16 + (lane >> 2);
        size_t base0 = ((size_t)b * S_ + row0) * E_ + h * 64 + 2 * (lane & 3);
        size_t base1 = base0 + (size_t)8 * E_;
        #pragma unroll
        for (int j = 0; j < 8; j++) {
            *(__half2*)(O + base0 + j * 8) = __floats2half2_rn(oc[mt][j][0] * i0,
                                                               oc[mt][j][1] * i0);
            *(__half2*)(O + base1 + j * 8) = __floats2half2_rn(oc[mt][j][2] * i1,
                                                               oc[mt][j][3] * i1);
        }
    }
}

// ---------------- host launcher ----------------
extern "C" void kernel_launch(void* const* d_in, const int* in_sizes, int n_in,
                              void* d_out, int out_size)
{
    const float* x   = (const float*)d_in[0];
    const float* Wq  = (const float*)d_in[1];
    const float* Wk  = (const float*)d_in[2];
    const float* Wv  = (const float*)d_in[3];
    const float* Wo  = (const float*)d_in[4];
    const float* bo  = (const float*)d_in[5];
    const float* W1  = (const float*)d_in[6];
    const float* b1  = (const float*)d_in[7];
    const float* W2  = (const float*)d_in[8];
    const float* b2  = (const float*)d_in[9];
    const float* g1  = (const float*)d_in[10];
    const float* be1 = (const float*)d_in[11];
    const float* g2  = (const float*)d_in[12];
    const float* be2 = (const float*)d_in[13];
    float* out = (float*)d_out;

    void *nx, *wqkv, *wo, *w1, *w2, *q, *k, *vt, *attn, *x1, *nx2, *ffn;
    cudaGetSymbolAddress(&nx, g_nx);
    cudaGetSymbolAddress(&wqkv, g_wqkv);
    cudaGetSymbolAddress(&wo, g_wo);
    cudaGetSymbolAddress(&w1, g_w1);
    cudaGetSymbolAddress(&w2, g_w2);
    cudaGetSymbolAddress(&q, g_q); cudaGetSymbolAddress(&k, g_k);
    cudaGetSymbolAddress(&vt, g_vt);
    cudaGetSymbolAddress(&attn, g_attn);
    cudaGetSymbolAddress(&x1, g_x1);
    cudaGetSymbolAddress(&nx2, g_nx2);
    cudaGetSymbolAddress(&ffn, g_ffn);

    cudaFuncSetAttribute(gemm_mma_kernel<0>, cudaFuncAttributeMaxDynamicSharedMemorySize, GEMM_SMEM);
    cudaFuncSetAttribute(gemm_mma_kernel<1>, cudaFuncAttributeMaxDynamicSharedMemorySize, GEMM_SMEM);
    cudaFuncSetAttribute(gemm_mma_kernel<2>, cudaFuncAttributeMaxDynamicSharedMemorySize, GEMM_SMEM);
    cudaFuncSetAttribute(gemm_mma_kernel<3>, cudaFuncAttributeMaxDynamicSharedMemorySize, GEMM_SMEM);
    cudaFuncSetAttribute(flash_kernel, cudaFuncAttributeMaxDynamicSharedMemorySize, FLASH_SMEM);

    // 1. weight transpose -> fp16
    wqkv_fp16_kernel<<<dim3(E_/32, NQKV/32), 256>>>(Wq, Wk, Wv, (__half*)wqkv);
    wt_fp16_kernel<<<dim3(E_/32, E_/32), 256>>>(Wo, E_, E_, (__half*)wo);
    wt_fp16_kernel<<<dim3(E_/32, FF_/32), 256>>>(W1, E_, FF_, (__half*)w1);
    wt_fp16_kernel<<<dim3(FF_/32, E_/32), 256>>>(W2, FF_, E_, (__half*)w2);
    // 2. LN1 -> fp16
    ln_fp16_kernel<<<TOK, 256>>>(x, g1, be1, (__half*)nx);
    // 3. fused QKV GEMM (N=3072) -> q,k fp16 [B,H,S,DH]; v fp16 [B,H,DH,S]
    gemm_mma_kernel<0><<<dim3(NQKV/128, TOK/128), 128, GEMM_SMEM>>>(
        (__half*)nx, (__half*)wqkv, nullptr, nullptr, nullptr, nullptr,
        (__half*)q, (__half*)k, (__half*)vt, E_, 0);
    // 4. HMMA flash attention -> attn fp16
    flash_kernel<<<dim3(S_/128, H_, B_), 128, FLASH_SMEM>>>(
        (__half*)q, (__half*)k, (__half*)vt, (__half*)attn);
    // 5. output projection + residual -> x1 fp32
    gemm_mma_kernel<1><<<dim3(E_/128, TOK/128), 128, GEMM_SMEM>>>(
        (__half*)attn, (__half*)wo, bo, x,
        (float*)x1, nullptr, nullptr, nullptr, nullptr, E_, E_);
    // 6. LN2 -> fp16
    ln_fp16_kernel<<<TOK, 256>>>((float*)x1, g2, be2, (__half*)nx2);
    // 7. FFN1: relu(+b1) -> ffn fp16
    gemm_mma_kernel<2><<<dim3(FF_/128, TOK/128), 128, GEMM_SMEM>>>(
        (__half*)nx2, (__half*)w1, b1, nullptr,
        nullptr, (__half*)ffn, nullptr, nullptr, nullptr, E_, FF_);
    // 8. FFN2: +b2 +x1 -> out
    gemm_mma_kernel<3><<<dim3(E_/128, TOK/128), 128, GEMM_SMEM>>>(
        (__half*)ffn, (__half*)w2, b2, (float*)x1,
        out, nullptr, nullptr, nullptr, nullptr, FF_, E_);
}

// round 15
// speedup vs baseline: 1.0576x; 1.0576x over previous
#include <cuda_runtime.h>
#include <cuda_fp16.h>
#include <cstdint>

#define B_   2
#define S_   2048
#define E_   1024
#define H_   16
#define DH_  64
#define FF_  4096
#define TOK  (B_*S_)   // 4096
#define NQKV 3072

// ---------------- scratch (no allocs allowed) ----------------
__device__ __half g_nx   [TOK*(size_t)E_];
__device__ __half g_wqkv [(size_t)NQKV*E_];
__device__ __half g_wo   [(size_t)E_*E_];
__device__ __half g_w1   [(size_t)FF_*E_];
__device__ __half g_w2   [(size_t)E_*FF_];
__device__ __half g_q [(size_t)B_*H_*S_*DH_];
__device__ __half g_k [(size_t)B_*H_*S_*DH_];
__device__ __half g_vt[(size_t)B_*H_*DH_*S_];   // V transposed: [B,H,DH,S]
__device__ __half g_attn[TOK*(size_t)E_];
__device__ float g_x1[TOK*(size_t)E_];
__device__ __half g_nx2 [TOK*(size_t)E_];
__device__ __half g_ffn [TOK*(size_t)FF_];

// ---------------- PTX helpers (base-target-safe: sm_80 features) -------------
__device__ __forceinline__ uint32_t smem_u32(const void* p) {
    uint32_t a;
    asm("{ .reg .u64 t; cvta.to.shared.u64 t, %1; cvt.u32.u64 %0, t; }" : "=r"(a) : "l"(p));
    return a;
}
__device__ __forceinline__ uint32_t h2_as_u32(__half2 h) {
    union { __half2 h2; uint32_t u; } cvt;
    cvt.h2 = h;
    return cvt.u;
}
__device__ __forceinline__ void cp16(uint32_t s, const void* g) {
    asm volatile("cp.async.cg.shared.global [%0], [%1], 16;" :: "r"(s), "l"(g));
}
#define CP_COMMIT() asm volatile("cp.async.commit_group;" ::: "memory")
#define CP_WAIT(n)  asm volatile("cp.async.wait_group %0;" :: "n"(n) : "memory")

__device__ __forceinline__ void ldm_x4(uint32_t& r0, uint32_t& r1, uint32_t& r2,
                                       uint32_t& r3, uint32_t a) {
    asm volatile("ldmatrix.sync.aligned.m8n8.x4.shared.b16 {%0,%1,%2,%3}, [%4];"
                 : "=r"(r0), "=r"(r1), "=r"(r2), "=r"(r3) : "r"(a));
}
__device__ __forceinline__ void mma16816(float* c, uint32_t a0, uint32_t a1,
                                         uint32_t a2, uint32_t a3,
                                         uint32_t b0, uint32_t b1) {
    asm volatile(
        "mma.sync.aligned.m16n8k16.row.col.f32.f16.f16.f32 "
        "{%0,%1,%2,%3},{%4,%5,%6,%7},{%8,%9},{%0,%1,%2,%3};"
        : "+f"(c[0]), "+f"(c[1]), "+f"(c[2]), "+f"(c[3])
        : "r"(a0), "r"(a1), "r"(a2), "r"(a3), "r"(b0), "r"(b1));
}

// fast 2^x on the FMA pipe (no MUFU). x clamped to [-125, ~0]. rel err ~1e-7.
__device__ __forceinline__ float fexp2(float x) {
    x = fmaxf(x, -125.0f);
    float t = x + 12582912.0f;              // 1.5*2^23: round-to-int in mantissa
    int n = __float_as_int(t) - 0x4B400000; // integer part
    float f = x - (t - 12582912.0f);        // frac in [-0.5, 0.5]
    float p =              1.5403530e-4f;
    p = fmaf(p, f, 1.3333558e-3f);
    p = fmaf(p, f, 9.6181291e-3f);
    p = fmaf(p, f, 5.5504109e-2f);
    p = fmaf(p, f, 2.4022651e-1f);
    p = fmaf(p, f, 6.9314718e-1f);
    p = fmaf(p, f, 1.0f);
    return p * __int_as_float((n + 127) << 23);
}

// ---------------- LayerNorm -> fp16: one block per token ---------------------
__global__ void __launch_bounds__(256) ln_fp16_kernel(
    const float* __restrict__ x, const float* __restrict__ g,
    const float* __restrict__ bta, __half* __restrict__ o)
{
    __shared__ float sh1[8], sh2[8];
    int tok = blockIdx.x;
    int t = threadIdx.x;
    const float4* xr = (const float4*)(x + (size_t)tok * E_);
    float4 v = xr[t];
    float sum = v.x + v.y + v.z + v.w;
    float sq  = v.x*v.x + v.y*v.y + v.z*v.z + v.w*v.w;
    #pragma unroll
    for (int o2 = 16; o2 > 0; o2 >>= 1) {
        sum += __shfl_xor_sync(0xffffffffu, sum, o2);
        sq  += __shfl_xor_sync(0xffffffffu, sq,  o2);
    }
    if ((t & 31) == 0) { sh1[t >> 5] = sum; sh2[t >> 5] = sq; }
    __syncthreads();
    if (t < 32) {
        sum = (t < 8) ? sh1[t] : 0.f;
        sq  = (t < 8) ? sh2[t] : 0.f;
        #pragma unroll
        for (int o2 = 4; o2 > 0; o2 >>= 1) {
            sum += __shfl_xor_sync(0xffffffffu, sum, o2);
            sq  += __shfl_xor_sync(0xffffffffu, sq,  o2);
        }
        if (t == 0) { sh1[0] = sum; sh2[0] = sq; }
    }
    __syncthreads();
    sum = sh1[0]; sq = sh2[0];
    float mu  = sum * (1.0f / E_);
    float var = sq * (1.0f / E_) - mu * mu;
    float rs  = rsqrtf(var + 1e-5f);
    float4 gv = ((const float4*)g)[t];
    float4 bv = ((const float4*)bta)[t];
    float a0 = (v.x - mu) * rs * gv.x + bv.x;
    float a1 = (v.y - mu) * rs * gv.y + bv.y;
    float a2 = (v.z - mu) * rs * gv.z + bv.z;
    float a3 = (v.w - mu) * rs * gv.w + bv.w;
    size_t base = (size_t)tok * E_ + t * 4;
    *(__half2*)(o + base)     = __floats2half2_rn(a0, a1);
    *(__half2*)(o + base + 2) = __floats2half2_rn(a2, a3);
}

// ---------------- weight transpose -> fp16: W[K,N] -> Wt[N,K] ----------------
// __half2 stores: each thread emits 2 adjacent k per store (halved STG count).
__global__ void __launch_bounds__(256) wt_fp16_kernel(
    const float* __restrict__ W, int K, int N, __half* __restrict__ o)
{
    __shared__ float t[32][33];
    int k0 = blockIdx.x * 32, n0 = blockIdx.y * 32;
    {
        int tx = threadIdx.x & 31, ty = threadIdx.x >> 5;
        #pragma unroll
        for (int r = 0; r < 4; r++)
            t[ty + 8*r][tx] = W[(size_t)(k0 + ty + 8*r) * N + n0 + tx];
    }
    __syncthreads();
    int txp = threadIdx.x & 15;        // k-pair index
    int tyn = threadIdx.x >> 4;        // 16 n rows
    #pragma unroll
    for (int r = 0; r < 2; r++) {
        int nn = tyn + 16 * r;
        __half2 v = __floats2half2_rn(t[2*txp][nn], t[2*txp + 1][nn]);
        *(__half2*)(o + (size_t)(n0 + nn) * K + k0 + 2*txp) = v;
    }
}

// QKV weights [H,E,DH] x3 -> fused Wt[3072, E] fp16 (__half2 stores)
__global__ void __launch_bounds__(256) wqkv_fp16_kernel(
    const float* __restrict__ Wq, const float* __restrict__ Wk,
    const float* __restrict__ Wv, __half* __restrict__ o)
{
    __shared__ float t[32][33];
    int e0 = blockIdx.x * 32, n0 = blockIdx.y * 32;
    const float* Wm = (n0 < 1024) ? Wq : (n0 < 2048) ? Wk : Wv;
    int nn0 = n0 & 1023;
    int h = nn0 >> 6, d0 = nn0 & 63;
    {
        int tx = threadIdx.x & 31, ty = threadIdx.x >> 5;
        #pragma unroll
        for (int r = 0; r < 4; r++)
            t[ty + 8*r][tx] = Wm[((size_t)h * E_ + e0 + ty + 8*r) * DH_ + d0 + tx];
    }
    __syncthreads();
    int txp = threadIdx.x & 15;
    int tyn = threadIdx.x >> 4;
    #pragma unroll
    for (int r = 0; r < 2; r++) {
        int nn = tyn + 16 * r;
        __half2 v = __floats2half2_rn(t[2*txp][nn], t[2*txp + 1][nn]);
        *(__half2*)(o + (size_t)(n0 + nn) * E_ + e0 + 2*txp) = v;
    }
}

// ---------------- HMMA GEMM: C[M,N] = A[M,K]*Bt[N,K]^T, plain fp16 -----------
// 128 threads, 4 warps, each warp 64x64. BK=32, 4 stages, distance-3 (R10).
#define BK     32
#define LDS    40
#define AELEMS (128 * LDS)
#define ABYTES (AELEMS * 2)            // 10240
#define STG_BYTES (2 * ABYTES)
#define GEMM_SMEM (4 * STG_BYTES)      // 81920 -> 2 CTA/SM

template<int MODE>
__global__ void __launch_bounds__(128, 2) gemm_mma_kernel(
    const __half* __restrict__ A, const __half* __restrict__ Bt,
    const float* __restrict__ bias, const float* __restrict__ res,
    float* __restrict__ o0, __half* __restrict__ oh,
    __half* __restrict__ q16, __half* __restrict__ k16, __half* __restrict__ v16,
    int K, int ldC)
{
    extern __shared__ __half smbuf[];
    const uint32_t sbase = smem_u32(smbuf);
    const int NIT = K / BK;
    const int t = threadIdx.x;
    const int wid = t >> 5, lane = t & 31;
    const int bm = blockIdx.y * 128, bn = blockIdx.x * 128;
    const int wm = (wid & 1) * 64, wn = (wid >> 1) * 64;

    const __half* Abase = A  + (size_t)bm * K;
    const __half* Bbase = Bt + (size_t)bn * K;

    auto load_stage = [&](int st, int i) {
        uint32_t sa = sbase + st * STG_BYTES;
        int kc = i * BK;
        #pragma unroll
        for (int p = 0; p < 4; p++) {
            int idx = t + p * 128;
            int row = idx >> 2, ch = idx & 3;
            uint32_t off = (uint32_t)(row * LDS + ch * 8) * 2;
            cp16(sa + off,          Abase + (size_t)row * K + kc + ch * 8);
            cp16(sa + ABYTES + off, Bbase + (size_t)row * K + kc + ch * 8);
        }
    };

    #pragma unroll
    for (int s = 0; s < 3; s++) { load_stage(s, s); CP_COMMIT(); }

    float c[4][8][4];
    #pragma unroll
    for (int mt = 0; mt < 4; mt++)
        #pragma unroll
        for (int nt = 0; nt < 8; nt++)
            #pragma unroll
            for (int e = 0; e < 4; e++) c[mt][nt][e] = 0.f;

    for (int i = 0; i < NIT; i++) {
        CP_WAIT(2);
        __syncthreads();
        if (i + 3 < NIT) load_stage((i + 3) & 3, i + 3);
        CP_COMMIT();

        uint32_t sa = sbase + (i & 3) * STG_BYTES;
        uint32_t sb = sa + ABYTES;
        #pragma unroll
        for (int ks = 0; ks < 2; ks++) {
            uint32_t a[4][4];
            #pragma unroll
            for (int mt = 0; mt < 4; mt++) {
                uint32_t addr = sa + (uint32_t)(((wm + mt*16 + (lane & 15)) * LDS
                                  + ks*16 + (lane >> 4) * 8) * 2);
                ldm_x4(a[mt][0], a[mt][1], a[mt][2], a[mt][3], addr);
            }
            uint32_t b[8][2];
            #pragma unroll
            for (int np = 0; np < 4; np++) {
                int nrow = wn + np*16 + (lane & 7) + ((lane >> 4) << 3);
                int ncol = ks*16 + (((lane >> 3) & 1) << 3);
                uint32_t addr = sb + (uint32_t)((nrow * LDS + ncol) * 2);
                uint32_t r0, r1, r2, r3;
                ldm_x4(r0, r1, r2, r3, addr);
                b[2*np][0] = r0; b[2*np][1] = r1;
                b[2*np+1][0] = r2; b[2*np+1][1] = r3;
            }
            #pragma unroll
            for (int mt = 0; mt < 4; mt++)
                #pragma unroll
                for (int nt = 0; nt < 8; nt++)
                    mma16816(c[mt][nt], a[mt][0], a[mt][1], a[mt][2], a[mt][3],
                             b[nt][0], b[nt][1]);
        }
    }

    // ---------------- epilogue ----------------
    const int r = lane >> 2, cq = (lane & 3) * 2;
    #pragma unroll
    for (int mt = 0; mt < 4; mt++) {
        #pragma unroll
        for (int half_ = 0; half_ < 2; half_++) {
            int m = bm + wm + mt * 16 + r + half_ * 8;
            #pragma unroll
            for (int nt = 0; nt < 8; nt++) {
                int n = bn + wn + nt * 8 + cq;
                float v0 = c[mt][nt][half_ * 2 + 0];
                float v1 = c[mt][nt][half_ * 2 + 1];
                if (MODE == 0) {
                    int mat = n >> 10;
                    int hh = (n & 1023) >> 6, d = n & 63;
                    int bb = m >> 11, srow = m & (S_ - 1);
                    if (mat < 2) {
                        __half* dst = (mat == 0) ? q16 : k16;
                        *(__half2*)(dst + (((size_t)(bb * H_ + hh) * S_ + srow) << 6) + d)
                            = __floats2half2_rn(v0, v1);
                    } else {
                        __half* p = v16 + ((size_t)(bb * H_ + hh) * DH_ + d) * S_ + srow;
                        p[0]  = __float2half_rn(v0);
                        p[S_] = __float2half_rn(v1);
                    }
                } else if (MODE == 2) {
                    float2 bv = *(const float2*)(bias + n);
                    v0 = fmaxf(v0 + bv.x, 0.f);
                    v1 = fmaxf(v1 + bv.y, 0.f);
                    *(__half2*)(oh + (size_t)m * ldC + n) = __floats2half2_rn(v0, v1);
                } else {
                    size_t base = (size_t)m * ldC + n;
                    float2 bv = *(const float2*)(bias + n);
                    float2 rv = *(const float2*)(res + base);
                    *(float2*)(o0 + base) = make_float2(v0 + bv.x + rv.x,
                                                        v1 + bv.y + rv.y);
                }
            }
        }
    }
}

// ---------------- HMMA flash attention (causal) -------------------------------
// 128 queries x 64 keys per tile, 4 warps (32 q-rows each), fp16 in, fp16 out.
#define FLDS 72
#define FLASH_SMEM ((128 + 4*64) * FLDS * 2)   // 55296 B

__global__ void __launch_bounds__(128, 2) flash_kernel(
    const __half* __restrict__ Q, const __half* __restrict__ Kp,
    const __half* __restrict__ Vt, __half* __restrict__ O)
{
    extern __shared__ __half fsm[];
    const uint32_t qb = smem_u32(fsm);                 // Q [128][72]
    const uint32_t kb = qb + 128 * FLDS * 2;           // K [2][64][72]
    const uint32_t vb = kb + 2 * 64 * FLDS * 2;        // Vt [2][64][72]

    const int qt = (int)gridDim.x - 1 - (int)blockIdx.x;   // heavy tiles first
    const int h = blockIdx.y, b = blockIdx.z;
    const int t = threadIdx.x, wid = t >> 5, lane = t & 31;
    const int wm = wid * 32;

    const __half* Qg = Q  + (((size_t)(b * H_ + h)) * S_ + qt * 128) * DH_;
    const __half* Kg = Kp + ((size_t)(b * H_ + h)) * S_ * DH_;
    const __half* Vg = Vt + ((size_t)(b * H_ + h)) * DH_ * S_;

    auto load_kv = [&](int kt) {
        uint32_t st = (uint32_t)(kt & 1) * 64 * FLDS * 2;
        #pragma unroll
        for (int p = 0; p < 4; p++) {
            int idx = t + p * 128;
            int row = idx >> 3, ch = idx & 7;
            uint32_t off = (uint32_t)(row * FLDS + ch * 8) * 2;
            cp16(kb + st + off, Kg + (size_t)(kt * 64 + row) * DH_ + ch * 8);
            cp16(vb + st + off, Vg + (size_t)row * S_ + kt * 64 + ch * 8);
        }
    };

    // Q + KV(0) in one group
    #pragma unroll
    for (int p = 0; p < 8; p++) {
        int idx = t + p * 128;
        int row = idx >> 3, ch = idx & 7;
        cp16(qb + (uint32_t)(row * FLDS + ch * 8) * 2, Qg + (size_t)row * DH_ + ch * 8);
    }
    load_kv(0);
    CP_COMMIT();

    const float alpha = 0.125f * 1.44269504f;   // scale * log2(e)
    float mrow[2][2], lrow[2][2];
    #pragma unroll
    for (int mt = 0; mt < 2; mt++) {
        mrow[mt][0] = -1e30f; mrow[mt][1] = -1e30f;
        lrow[mt][0] = 0.f;    lrow[mt][1] = 0.f;
    }
    float oc[2][8][4];
    #pragma unroll
    for (int mt = 0; mt < 2; mt++)
        #pragma unroll
        for (int j = 0; j < 8; j++)
            #pragma unroll
            for (int e = 0; e < 4; e++) oc[mt][j][e] = 0.f;

    uint32_t qa[2][4][4];
    const int nkt = 2 * qt + 2;

    for (int kt = 0; kt < nkt; kt++) {
        if (kt + 1 < nkt) { load_kv(kt + 1); CP_COMMIT(); CP_WAIT(1); }
        else              { CP_WAIT(0); }
        __syncthreads();

        if (kt == 0) {   // Q fragments, loaded once
            #pragma unroll
            for (int mt = 0; mt < 2; mt++)
                #pragma unroll
                for (int ks = 0; ks < 4; ks++) {
                    uint32_t addr = qb + (uint32_t)(((wm + mt*16 + (lane & 15)) * FLDS
                                       + ks * 16 + (lane >> 4) * 8) * 2);
                    ldm_x4(qa[mt][ks][0], qa[mt][ks][1], qa[mt][ks][2], qa[mt][ks][3], addr);
                }
        }

        // ---- S = Q K^T ----
        float sc[2][8][4];
        #pragma unroll
        for (int mt = 0; mt < 2; mt++)
            #pragma unroll
            for (int j = 0; j < 8; j++)
                #pragma unroll
                for (int e = 0; e < 4; e++) sc[mt][j][e] = 0.f;

        uint32_t kbs = kb + (uint32_t)(kt & 1) * 64 * FLDS * 2;
        #pragma unroll
        for (int ks = 0; ks < 4; ks++) {
            uint32_t bfr[8][2];
            #pragma unroll
            for (int np = 0; np < 4; np++) {
                int nrow = np * 16 + (lane & 7) + ((lane >> 4) << 3);
                int ncol = ks * 16 + (((lane >> 3) & 1) << 3);
                uint32_t r0, r1, r2, r3;
                ldm_x4(r0, r1, r2, r3, kbs + (uint32_t)((nrow * FLDS + ncol) * 2));
                bfr[2*np][0] = r0; bfr[2*np][1] = r1;
                bfr[2*np+1][0] = r2; bfr[2*np+1][1] = r3;
            }
            #pragma unroll
            for (int mt = 0; mt < 2; mt++)
                #pragma unroll
                for (int j = 0; j < 8; j++)
                    mma16816(sc[mt][j], qa[mt][ks][0], qa[mt][ks][1],
                             qa[mt][ks][2], qa[mt][ks][3], bfr[j][0], bfr[j][1]);
        }

        // ---- causal mask (only diagonal key tiles) ----
        if (kt >= 2 * qt) {
            #pragma unroll
            for (int mt = 0; mt < 2; mt++) {
                int row0 = qt * 128 + wm + mt * 16 + (lane >> 2);
                int colb = kt * 64 + 2 * (lane & 3);
                #pragma unroll
                for (int j = 0; j < 8; j++) {
                    #pragma unroll
                    for (int cc = 0; cc < 2; cc++) {
                        int col = colb + j * 8 + cc;
                        if (col > row0)     sc[mt][j][cc]     = -1e30f;
                        if (col > row0 + 8) sc[mt][j][2 + cc] = -1e30f;
                    }
                }
            }
        }

        // ---- online softmax + P packing ----
        uint32_t pa[2][4][4];
        float corr[2][2];
        #pragma unroll
        for (int mt = 0; mt < 2; mt++) {
            float mx0 = -1e30f, mx1 = -1e30f;
            #pragma unroll
            for (int j = 0; j < 8; j++) {
                mx0 = fmaxf(mx0, fmaxf(sc[mt][j][0], sc[mt][j][1]));
                mx1 = fmaxf(mx1, fmaxf(sc[mt][j][2], sc[mt][j][3]));
            }
            mx0 = fmaxf(mx0, __shfl_xor_sync(0xffffffffu, mx0, 1));
            mx0 = fmaxf(mx0, __shfl_xor_sync(0xffffffffu, mx0, 2));
            mx1 = fmaxf(mx1, __shfl_xor_sync(0xffffffffu, mx1, 1));
            mx1 = fmaxf(mx1, __shfl_xor_sync(0xffffffffu, mx1, 2));
            float nm0 = fmaxf(mrow[mt][0], mx0), nm1 = fmaxf(mrow[mt][1], mx1);
            corr[mt][0] = fexp2((mrow[mt][0] - nm0) * alpha);
            corr[mt][1] = fexp2((mrow[mt][1] - nm1) * alpha);
            mrow[mt][0] = nm0; mrow[mt][1] = nm1;
            float ma0 = nm0 * alpha, ma1 = nm1 * alpha;

            float rs0 = 0.f, rs1 = 0.f;
            #pragma unroll
            for (int j = 0; j < 8; j++) {
                float p0 = fexp2(fmaf(sc[mt][j][0], alpha, -ma0));
                float p1 = fexp2(fmaf(sc[mt][j][1], alpha, -ma0));
                float p2 = fexp2(fmaf(sc[mt][j][2], alpha, -ma1));
                float p3 = fexp2(fmaf(sc[mt][j][3], alpha, -ma1));
                rs0 += p0 + p1; rs1 += p2 + p3;
                int ks = j >> 1, hi = (j & 1) << 1;
                pa[mt][ks][hi]     = h2_as_u32(__floats2half2_rn(p0, p1));
                pa[mt][ks][hi + 1] = h2_as_u32(__floats2half2_rn(p2, p3));
            }
            rs0 += __shfl_xor_sync(0xffffffffu, rs0, 1);
            rs0 += __shfl_xor_sync(0xffffffffu, rs0, 2);
            rs1 += __shfl_xor_sync(0xffffffffu, rs1, 1);
            rs1 += __shfl_xor_sync(0xffffffffu, rs1, 2);
            lrow[mt][0] = lrow[mt][0] * corr[mt][0] + rs0;
            lrow[mt][1] = lrow[mt][1] * corr[mt][1] + rs1;
            #pragma unroll
            for (int j = 0; j < 8; j++) {
                oc[mt][j][0] *= corr[mt][0]; oc[mt][j][1] *= corr[mt][0];
                oc[mt][j][2] *= corr[mt][1]; oc[mt][j][3] *= corr[mt][1];
            }
        }

        // ---- O += P V ----
        uint32_t vbs = vb + (uint32_t)(kt & 1) * 64 * FLDS * 2;
        #pragma unroll
        for (int ks = 0; ks < 4; ks++) {
            uint32_t vfr[8][2];
            #pragma unroll
            for (int np = 0; np < 4; np++) {
                int nrow = np * 16 + (lane & 7) + ((lane >> 4) << 3);
                int ncol = ks * 16 + (((lane >> 3) & 1) << 3);
                uint32_t r0, r1, r2, r3;
                ldm_x4(r0, r1, r2, r3, vbs + (uint32_t)((nrow * FLDS + ncol) * 2));
                vfr[2*np][0] = r0; vfr[2*np][1] = r1;
                vfr[2*np+1][0] = r2; vfr[2*np+1][1] = r3;
            }
            #pragma unroll
            for (int mt = 0; mt < 2; mt++)
                #pragma unroll
                for (int j = 0; j < 8; j++)
                    mma16816(oc[mt][j], pa[mt][ks][0], pa[mt][ks][1],
                             pa[mt][ks][2], pa[mt][ks][3], vfr[j][0], vfr[j][1]);
        }
        __syncthreads();
    }

    // ---- write O (concat layout, fp16) ----
    #pragma unroll
    for (int mt = 0; mt < 2; mt++) {
        float i0 = 1.0f / lrow[mt][0], i1 = 1.0f / lrow[mt][1];
        int row0 = qt * 128 + wm + mt * 16 + (lane >> 2);
        size_t base0 = ((size_t)b * S_ + row0) * E_ + h * 64 + 2 * (lane & 3);
        size_t base1 = base0 + (size_t)8 * E_;
        #pragma unroll
        for (int j = 0; j < 8; j++) {
            *(__half2*)(O + base0 + j * 8) = __floats2half2_rn(oc[mt][j][0] * i0,
                                                               oc[mt][j][1] * i0);
            *(__half2*)(O + base1 + j * 8) = __floats2half2_rn(oc[mt][j][2] * i1,
                                                               oc[mt][j][3] * i1);
        }
    }
}

// ---------------- host launcher ----------------
extern "C" void kernel_launch(void* const* d_in, const int* in_sizes, int n_in,
                              void* d_out, int out_size)
{
    const float* x   = (const float*)d_in[0];
    const float* Wq  = (const float*)d_in[1];
    const float* Wk  = (const float*)d_in[2];
    const float* Wv  = (const float*)d_in[3];
    const float* Wo  = (const float*)d_in[4];
    const float* bo  = (const float*)d_in[5];
    const float* W1  = (const float*)d_in[6];
    const float* b1  = (const float*)d_in[7];
    const float* W2  = (const float*)d_in[8];
    const float* b2  = (const float*)d_in[9];
    const float* g1  = (const float*)d_in[10];
    const float* be1 = (const float*)d_in[11];
    const float* g2  = (const float*)d_in[12];
    const float* be2 = (const float*)d_in[13];
    float* out = (float*)d_out;

    void *nx, *wqkv, *wo, *w1, *w2, *q, *k, *vt, *attn, *x1, *nx2, *ffn;
    cudaGetSymbolAddress(&nx, g_nx);
    cudaGetSymbolAddress(&wqkv, g_wqkv);
    cudaGetSymbolAddress(&wo, g_wo);
    cudaGetSymbolAddress(&w1, g_w1);
    cudaGetSymbolAddress(&w2, g_w2);
    cudaGetSymbolAddress(&q, g_q); cudaGetSymbolAddress(&k, g_k);
    cudaGetSymbolAddress(&vt, g_vt);
    cudaGetSymbolAddress(&attn, g_attn);
    cudaGetSymbolAddress(&x1, g_x1);
    cudaGetSymbolAddress(&nx2, g_nx2);
    cudaGetSymbolAddress(&ffn, g_ffn);

    cudaFuncSetAttribute(gemm_mma_kernel<0>, cudaFuncAttributeMaxDynamicSharedMemorySize, GEMM_SMEM);
    cudaFuncSetAttribute(gemm_mma_kernel<1>, cudaFuncAttributeMaxDynamicSharedMemorySize, GEMM_SMEM);
    cudaFuncSetAttribute(gemm_mma_kernel<2>, cudaFuncAttributeMaxDynamicSharedMemorySize, GEMM_SMEM);
    cudaFuncSetAttribute(gemm_mma_kernel<3>, cudaFuncAttributeMaxDynamicSharedMemorySize, GEMM_SMEM);
    cudaFuncSetAttribute(flash_kernel, cudaFuncAttributeMaxDynamicSharedMemorySize, FLASH_SMEM);

    // 1. weight transpose -> fp16
    wqkv_fp16_kernel<<<dim3(E_/32, NQKV/32), 256>>>(Wq, Wk, Wv, (__half*)wqkv);
    wt_fp16_kernel<<<dim3(E_/32, E_/32), 256>>>(Wo, E_, E_, (__half*)wo);
    wt_fp16_kernel<<<dim3(E_/32, FF_/32), 256>>>(W1, E_, FF_, (__half*)w1);
    wt_fp16_kernel<<<dim3(FF_/32, E_/32), 256>>>(W2, FF_, E_, (__half*)w2);
    // 2. LN1 -> fp16
    ln_fp16_kernel<<<TOK, 256>>>(x, g1, be1, (__half*)nx);
    // 3. fused QKV GEMM (N=3072) -> q,k fp16 [B,H,S,DH]; v fp16 [B,H,DH,S]
    gemm_mma_kernel<0><<<dim3(NQKV/128, TOK/128), 128, GEMM_SMEM>>>(
        (__half*)nx, (__half*)wqkv, nullptr, nullptr, nullptr, nullptr,
        (__half*)q, (__half*)k, (__half*)vt, E_, 0);
    // 4. HMMA flash attention -> attn fp16
    flash_kernel<<<dim3(S_/128, H_, B_), 128, FLASH_SMEM>>>(
        (__half*)q, (__half*)k, (__half*)vt, (__half*)attn);
    // 5. output projection + residual -> x1 fp32
    gemm_mma_kernel<1><<<dim3(E_/128, TOK/128), 128, GEMM_SMEM>>>(
        (__half*)attn, (__half*)wo, bo, x,
        (float*)x1, nullptr, nullptr, nullptr, nullptr, E_, E_);
    // 6. LN2 -> fp16
    ln_fp16_kernel<<<TOK, 256>>>((float*)x1, g2, be2, (__half*)nx2);
    // 7. FFN1: relu(+b1) -> ffn fp16
    gemm_mma_kernel<2><<<dim3(FF_/128, TOK/128), 128, GEMM_SMEM>>>(
        (__half*)nx2, (__half*)w1, b1, nullptr,
        nullptr, (__half*)ffn, nullptr, nullptr, nullptr, E_, FF_);
    // 8. FFN2: +b2 +x1 -> out
    gemm_mma_kernel<3><<<dim3(E_/128, TOK/128), 128, GEMM_SMEM>>>(
        (__half*)ffn, (__half*)w2, b2, (float*)x1,
        out, nullptr, nullptr, nullptr, nullptr, FF_, E_);
}

// round 16
// speedup vs baseline: 1.0621x; 1.0043x over previous
#include <cuda_runtime.h>
#include <cuda_fp16.h>
#include <cstdint>

#define B_   2
#define S_   2048
#define E_   1024
#define H_   16
#define DH_  64
#define FF_  4096
#define TOK  (B_*S_)   // 4096
#define NQKV 3072

// ---------------- scratch (no allocs allowed) ----------------
__device__ __half g_nx   [TOK*(size_t)E_];
__device__ __half g_wqkv [(size_t)NQKV*E_];
__device__ __half g_wo   [(size_t)E_*E_];
__device__ __half g_w1   [(size_t)FF_*E_];
__device__ __half g_w2   [(size_t)E_*FF_];
__device__ __half g_q [(size_t)B_*H_*S_*DH_];
__device__ __half g_k [(size_t)B_*H_*S_*DH_];
__device__ __half g_vt[(size_t)B_*H_*DH_*S_];   // V transposed: [B,H,DH,S]
__device__ __half g_attn[TOK*(size_t)E_];
__device__ float g_x1[TOK*(size_t)E_];
__device__ __half g_nx2 [TOK*(size_t)E_];
__device__ __half g_ffn [TOK*(size_t)FF_];

// ---------------- PTX helpers (base-target-safe: sm_80 features) -------------
__device__ __forceinline__ uint32_t smem_u32(const void* p) {
    uint32_t a;
    asm("{ .reg .u64 t; cvta.to.shared.u64 t, %1; cvt.u32.u64 %0, t; }" : "=r"(a) : "l"(p));
    return a;
}
__device__ __forceinline__ uint32_t h2_as_u32(__half2 h) {
    union { __half2 h2; uint32_t u; } cvt;
    cvt.h2 = h;
    return cvt.u;
}
__device__ __forceinline__ void cp16(uint32_t s, const void* g) {
    asm volatile("cp.async.cg.shared.global [%0], [%1], 16;" :: "r"(s), "l"(g));
}
#define CP_COMMIT() asm volatile("cp.async.commit_group;" ::: "memory")
#define CP_WAIT(n)  asm volatile("cp.async.wait_group %0;" :: "n"(n) : "memory")

__device__ __forceinline__ void ldm_x4(uint32_t& r0, uint32_t& r1, uint32_t& r2,
                                       uint32_t& r3, uint32_t a) {
    asm volatile("ldmatrix.sync.aligned.m8n8.x4.shared.b16 {%0,%1,%2,%3}, [%4];"
                 : "=r"(r0), "=r"(r1), "=r"(r2), "=r"(r3) : "r"(a));
}
__device__ __forceinline__ void mma16816(float* c, uint32_t a0, uint32_t a1,
                                         uint32_t a2, uint32_t a3,
                                         uint32_t b0, uint32_t b1) {
    asm volatile(
        "mma.sync.aligned.m16n8k16.row.col.f32.f16.f16.f32 "
        "{%0,%1,%2,%3},{%4,%5,%6,%7},{%8,%9},{%0,%1,%2,%3};"
        : "+f"(c[0]), "+f"(c[1]), "+f"(c[2]), "+f"(c[3])
        : "r"(a0), "r"(a1), "r"(a2), "r"(a3), "r"(b0), "r"(b1));
}

// fast 2^x on the FMA pipe (no MUFU). x clamped to [-125, ~0]. rel err ~1e-7.
__device__ __forceinline__ float fexp2(float x) {
    x = fmaxf(x, -125.0f);
    float t = x + 12582912.0f;              // 1.5*2^23: round-to-int in mantissa
    int n = __float_as_int(t) - 0x4B400000; // integer part
    float f = x - (t - 12582912.0f);        // frac in [-0.5, 0.5]
    float p =              1.5403530e-4f;
    p = fmaf(p, f, 1.3333558e-3f);
    p = fmaf(p, f, 9.6181291e-3f);
    p = fmaf(p, f, 5.5504109e-2f);
    p = fmaf(p, f, 2.4022651e-1f);
    p = fmaf(p, f, 6.9314718e-1f);
    p = fmaf(p, f, 1.0f);
    return p * __int_as_float((n + 127) << 23);
}

// ---------------- LayerNorm -> fp16: one block per token ---------------------
__global__ void __launch_bounds__(256) ln_fp16_kernel(
    const float* __restrict__ x, const float* __restrict__ g,
    const float* __restrict__ bta, __half* __restrict__ o)
{
    __shared__ float sh1[8], sh2[8];
    int tok = blockIdx.x;
    int t = threadIdx.x;
    const float4* xr = (const float4*)(x + (size_t)tok * E_);
    float4 v = xr[t];
    float sum = v.x + v.y + v.z + v.w;
    float sq  = v.x*v.x + v.y*v.y + v.z*v.z + v.w*v.w;
    #pragma unroll
    for (int o2 = 16; o2 > 0; o2 >>= 1) {
        sum += __shfl_xor_sync(0xffffffffu, sum, o2);
        sq  += __shfl_xor_sync(0xffffffffu, sq,  o2);
    }
    if ((t & 31) == 0) { sh1[t >> 5] = sum; sh2[t >> 5] = sq; }
    __syncthreads();
    if (t < 32) {
        sum = (t < 8) ? sh1[t] : 0.f;
        sq  = (t < 8) ? sh2[t] : 0.f;
        #pragma unroll
        for (int o2 = 4; o2 > 0; o2 >>= 1) {
            sum += __shfl_xor_sync(0xffffffffu, sum, o2);
            sq  += __shfl_xor_sync(0xffffffffu, sq,  o2);
        }
        if (t == 0) { sh1[0] = sum; sh2[0] = sq; }
    }
    __syncthreads();
    sum = sh1[0]; sq = sh2[0];
    float mu  = sum * (1.0f / E_);
    float var = sq * (1.0f / E_) - mu * mu;
    float rs  = rsqrtf(var + 1e-5f);
    float4 gv = ((const float4*)g)[t];
    float4 bv = ((const float4*)bta)[t];
    float a0 = (v.x - mu) * rs * gv.x + bv.x;
    float a1 = (v.y - mu) * rs * gv.y + bv.y;
    float a2 = (v.z - mu) * rs * gv.z + bv.z;
    float a3 = (v.w - mu) * rs * gv.w + bv.w;
    size_t base = (size_t)tok * E_ + t * 4;
    *(__half2*)(o + base)     = __floats2half2_rn(a0, a1);
    *(__half2*)(o + base + 2) = __floats2half2_rn(a2, a3);
}

// ---------------- weight transpose -> fp16: W[K,N] -> Wt[N,K] ----------------
__global__ void __launch_bounds__(256) wt_fp16_kernel(
    const float* __restrict__ W, int K, int N, __half* __restrict__ o)
{
    __shared__ float t[32][33];
    int k0 = blockIdx.x * 32, n0 = blockIdx.y * 32;
    {
        int tx = threadIdx.x & 31, ty = threadIdx.x >> 5;
        #pragma unroll
        for (int r = 0; r < 4; r++)
            t[ty + 8*r][tx] = W[(size_t)(k0 + ty + 8*r) * N + n0 + tx];
    }
    __syncthreads();
    int txp = threadIdx.x & 15;        // k-pair index
    int tyn = threadIdx.x >> 4;        // 16 n rows
    #pragma unroll
    for (int r = 0; r < 2; r++) {
        int nn = tyn + 16 * r;
        __half2 v = __floats2half2_rn(t[2*txp][nn], t[2*txp + 1][nn]);
        *(__half2*)(o + (size_t)(n0 + nn) * K + k0 + 2*txp) = v;
    }
}

// QKV weights [H,E,DH] x3 -> fused Wt[3072, E] fp16 (__half2 stores)
__global__ void __launch_bounds__(256) wqkv_fp16_kernel(
    const float* __restrict__ Wq, const float* __restrict__ Wk,
    const float* __restrict__ Wv, __half* __restrict__ o)
{
    __shared__ float t[32][33];
    int e0 = blockIdx.x * 32, n0 = blockIdx.y * 32;
    const float* Wm = (n0 < 1024) ? Wq : (n0 < 2048) ? Wk : Wv;
    int nn0 = n0 & 1023;
    int h = nn0 >> 6, d0 = nn0 & 63;
    {
        int tx = threadIdx.x & 31, ty = threadIdx.x >> 5;
        #pragma unroll
        for (int r = 0; r < 4; r++)
            t[ty + 8*r][tx] = Wm[((size_t)h * E_ + e0 + ty + 8*r) * DH_ + d0 + tx];
    }
    __syncthreads();
    int txp = threadIdx.x & 15;
    int tyn = threadIdx.x >> 4;
    #pragma unroll
    for (int r = 0; r < 2; r++) {
        int nn = tyn + 16 * r;
        __half2 v = __floats2half2_rn(t[2*txp][nn], t[2*txp + 1][nn]);
        *(__half2*)(o + (size_t)(n0 + nn) * E_ + e0 + 2*txp) = v;
    }
}

// ---------------- HMMA GEMM: C[M,N] = A[M,K]*Bt[N,K]^T, plain fp16 -----------
// 128 threads, 4 warps, each warp 64x64. BK=32, 4 stages, distance-3 (R10).
#define BK     32
#define LDS    40
#define AELEMS (128 * LDS)
#define ABYTES (AELEMS * 2)            // 10240
#define STG_BYTES (2 * ABYTES)
#define GEMM_SMEM (4 * STG_BYTES)      // 81920 -> 2 CTA/SM
#define VSTG   136                     // V staging stride (halves)

template<int MODE>
__global__ void __launch_bounds__(128, 2) gemm_mma_kernel(
    const __half* __restrict__ A, const __half* __restrict__ Bt,
    const float* __restrict__ bias, const float* __restrict__ res,
    float* __restrict__ o0, __half* __restrict__ oh,
    __half* __restrict__ q16, __half* __restrict__ k16, __half* __restrict__ v16,
    int K, int ldC)
{
    extern __shared__ __half smbuf[];
    const uint32_t sbase = smem_u32(smbuf);
    const int NIT = K / BK;
    const int t = threadIdx.x;
    const int wid = t >> 5, lane = t & 31;
    const int bm = blockIdx.y * 128, bn = blockIdx.x * 128;
    const int wm = (wid & 1) * 64, wn = (wid >> 1) * 64;

    const __half* Abase = A  + (size_t)bm * K;
    const __half* Bbase = Bt + (size_t)bn * K;

    auto load_stage = [&](int st, int i) {
        uint32_t sa = sbase + st * STG_BYTES;
        int kc = i * BK;
        #pragma unroll
        for (int p = 0; p < 4; p++) {
            int idx = t + p * 128;
            int row = idx >> 2, ch = idx & 3;
            uint32_t off = (uint32_t)(row * LDS + ch * 8) * 2;
            cp16(sa + off,          Abase + (size_t)row * K + kc + ch * 8);
            cp16(sa + ABYTES + off, Bbase + (size_t)row * K + kc + ch * 8);
        }
    };

    #pragma unroll
    for (int s = 0; s < 3; s++) { load_stage(s, s); CP_COMMIT(); }

    float c[4][8][4];
    #pragma unroll
    for (int mt = 0; mt < 4; mt++)
        #pragma unroll
        for (int nt = 0; nt < 8; nt++)
            #pragma unroll
            for (int e = 0; e < 4; e++) c[mt][nt][e] = 0.f;

    for (int i = 0; i < NIT; i++) {
        CP_WAIT(2);
        __syncthreads();
        if (i + 3 < NIT) load_stage((i + 3) & 3, i + 3);
        CP_COMMIT();

        uint32_t sa = sbase + (i & 3) * STG_BYTES;
        uint32_t sb = sa + ABYTES;
        #pragma unroll
        for (int ks = 0; ks < 2; ks++) {
            uint32_t a[4][4];
            #pragma unroll
            for (int mt = 0; mt < 4; mt++) {
                uint32_t addr = sa + (uint32_t)(((wm + mt*16 + (lane & 15)) * LDS
                                  + ks*16 + (lane >> 4) * 8) * 2);
                ldm_x4(a[mt][0], a[mt][1], a[mt][2], a[mt][3], addr);
            }
            uint32_t b[8][2];
            #pragma unroll
            for (int np = 0; np < 4; np++) {
                int nrow = wn + np*16 + (lane & 7) + ((lane >> 4) << 3);
                int ncol = ks*16 + (((lane >> 3) & 1) << 3);
                uint32_t addr = sb + (uint32_t)((nrow * LDS + ncol) * 2);
                uint32_t r0, r1, r2, r3;
                ldm_x4(r0, r1, r2, r3, addr);
                b[2*np][0] = r0; b[2*np][1] = r1;
                b[2*np+1][0] = r2; b[2*np+1][1] = r3;
            }
            #pragma unroll
            for (int mt = 0; mt < 4; mt++)
                #pragma unroll
                for (int nt = 0; nt < 8; nt++)
                    mma16816(c[mt][nt], a[mt][0], a[mt][1], a[mt][2], a[mt][3],
                             b[nt][0], b[nt][1]);
        }
    }

    // ---------------- epilogue ----------------
    const int r = lane >> 2, cq = (lane & 3) * 2;

    if (MODE == 0 && bn >= 2048) {
        // ---- V tile: stage transposed in smem, then coalesced writeout ----
        // (bn is 128-aligned and the q/k/v boundary is at 1024 -> whole CTA is V;
        //  branch is uniform across the CTA, so __syncthreads is safe)
        __syncthreads();   // all warps done reading pipeline stages
        #pragma unroll
        for (int mt = 0; mt < 4; mt++) {
            #pragma unroll
            for (int half_ = 0; half_ < 2; half_++) {
                int ml = wm + mt * 16 + r + half_ * 8;
                #pragma unroll
                for (int nt = 0; nt < 8; nt++) {
                    int nl = wn + nt * 8 + cq;
                    smbuf[(nl)     * VSTG + ml] = __float2half_rn(c[mt][nt][half_ * 2 + 0]);
                    smbuf[(nl + 1) * VSTG + ml] = __float2half_rn(c[mt][nt][half_ * 2 + 1]);
                }
            }
        }
        __syncthreads();
        // writeout: 128 rows (n_local) x 128 halves (m_local), 16B chunks.
        // 16 consecutive threads cover one row's 256B -> fully coalesced.
        const int bb = bm >> 11;
        const int srow0 = bm & (S_ - 1);
        const int hh_base = (bn & 1023) >> 6;
        #pragma unroll
        for (int p = 0; p < 16; p++) {
            int ci  = t + p * 128;
            int row = ci >> 4;           // n_local = 0..127
            int ch  = ci & 15;           // 16B chunk within row
            int hh  = hh_base + (row >> 6);
            int d   = row & 63;
            uint4 val = *(uint4*)(smbuf + row * VSTG + ch * 8);
            *(uint4*)(v16 + ((size_t)(bb * H_ + hh) * DH_ + d) * S_ + srow0 + ch * 8) = val;
        }
        return;
    }

    #pragma unroll
    for (int mt = 0; mt < 4; mt++) {
        #pragma unroll
        for (int half_ = 0; half_ < 2; half_++) {
            int m = bm + wm + mt * 16 + r + half_ * 8;
            #pragma unroll
            for (int nt = 0; nt < 8; nt++) {
                int n = bn + wn + nt * 8 + cq;
                float v0 = c[mt][nt][half_ * 2 + 0];
                float v1 = c[mt][nt][half_ * 2 + 1];
                if (MODE == 0) {
                    // q or k only (V handled above)
                    int mat = n >> 10;
                    int hh = (n & 1023) >> 6, d = n & 63;
                    int bb = m >> 11, srow = m & (S_ - 1);
                    __half* dst = (mat == 0) ? q16 : k16;
                    *(__half2*)(dst + (((size_t)(bb * H_ + hh) * S_ + srow) << 6) + d)
                        = __floats2half2_rn(v0, v1);
                } else if (MODE == 2) {
                    float2 bv = *(const float2*)(bias + n);
                    v0 = fmaxf(v0 + bv.x, 0.f);
                    v1 = fmaxf(v1 + bv.y, 0.f);
                    *(__half2*)(oh + (size_t)m * ldC + n) = __floats2half2_rn(v0, v1);
                } else {
                    size_t base = (size_t)m * ldC + n;
                    float2 bv = *(const float2*)(bias + n);
                    float2 rv = *(const float2*)(res + base);
                    *(float2*)(o0 + base) = make_float2(v0 + bv.x + rv.x,
                                                        v1 + bv.y + rv.y);
                }
            }
        }
    }
}

// ---------------- HMMA flash attention (causal) -------------------------------
// 128 queries x 64 keys per tile, 4 warps (32 q-rows each), fp16 in, fp16 out.
#define FLDS 72
#define FLASH_SMEM ((128 + 4*64) * FLDS * 2)   // 55296 B

__global__ void __launch_bounds__(128, 2) flash_kernel(
    const __half* __restrict__ Q, const __half* __restrict__ Kp,
    const __half* __restrict__ Vt, __half* __restrict__ O)
{
    extern __shared__ __half fsm[];
    const uint32_t qb = smem_u32(fsm);                 // Q [128][72]
    const uint32_t kb = qb + 128 * FLDS * 2;           // K [2][64][72]
    const uint32_t vb = kb + 2 * 64 * FLDS * 2;        // Vt [2][64][72]

    const int qt = (int)gridDim.x - 1 - (int)blockIdx.x;   // heavy tiles first
    const int h = blockIdx.y, b = blockIdx.z;
    const int t = threadIdx.x, wid = t >> 5, lane = t & 31;
    const int wm = wid * 32;

    const __half* Qg = Q  + (((size_t)(b * H_ + h)) * S_ + qt * 128) * DH_;
    const __half* Kg = Kp + ((size_t)(b * H_ + h)) * S_ * DH_;
    const __half* Vg = Vt + ((size_t)(b * H_ + h)) * DH_ * S_;

    auto load_kv = [&](int kt) {
        uint32_t st = (uint32_t)(kt & 1) * 64 * FLDS * 2;
        #pragma unroll
        for (int p = 0; p < 4; p++) {
            int idx = t + p * 128;
            int row = idx >> 3, ch = idx & 7;
            uint32_t off = (uint32_t)(row * FLDS + ch * 8) * 2;
            cp16(kb + st + off, Kg + (size_t)(kt * 64 + row) * DH_ + ch * 8);
            cp16(vb + st + off, Vg + (size_t)row * S_ + kt * 64 + ch * 8);
        }
    };

    // Q + KV(0) in one group
    #pragma unroll
    for (int p = 0; p < 8; p++) {
        int idx = t + p * 128;
        int row = idx >> 3, ch = idx & 7;
        cp16(qb + (uint32_t)(row * FLDS + ch * 8) * 2, Qg + (size_t)row * DH_ + ch * 8);
    }
    load_kv(0);
    CP_COMMIT();

    const float alpha = 0.125f * 1.44269504f;   // scale * log2(e)
    float mrow[2][2], lrow[2][2];
    #pragma unroll
    for (int mt = 0; mt < 2; mt++) {
        mrow[mt][0] = -1e30f; mrow[mt][1] = -1e30f;
        lrow[mt][0] = 0.f;    lrow[mt][1] = 0.f;
    }
    float oc[2][8][4];
    #pragma unroll
    for (int mt = 0; mt < 2; mt++)
        #pragma unroll
        for (int j = 0; j < 8; j++)
            #pragma unroll
            for (int e = 0; e < 4; e++) oc[mt][j][e] = 0.f;

    uint32_t qa[2][4][4];
    const int nkt = 2 * qt + 2;

    for (int kt = 0; kt < nkt; kt++) {
        if (kt + 1 < nkt) { load_kv(kt + 1); CP_COMMIT(); CP_WAIT(1); }
        else              { CP_WAIT(0); }
        __syncthreads();

        if (kt == 0) {   // Q fragments, loaded once
            #pragma unroll
            for (int mt = 0; mt < 2; mt++)
                #pragma unroll
                for (int ks = 0; ks < 4; ks++) {
                    uint32_t addr = qb + (uint32_t)(((wm + mt*16 + (lane & 15)) * FLDS
                                       + ks * 16 + (lane >> 4) * 8) * 2);
                    ldm_x4(qa[mt][ks][0], qa[mt][ks][1], qa[mt][ks][2], qa[mt][ks][3], addr);
                }
        }

        // ---- S = Q K^T ----
        float sc[2][8][4];
        #pragma unroll
        for (int mt = 0; mt < 2; mt++)
            #pragma unroll
            for (int j = 0; j < 8; j++)
                #pragma unroll
                for (int e = 0; e < 4; e++) sc[mt][j][e] = 0.f;

        uint32_t kbs = kb + (uint32_t)(kt & 1) * 64 * FLDS * 2;
        #pragma unroll
        for (int ks = 0; ks < 4; ks++) {
            uint32_t bfr[8][2];
            #pragma unroll
            for (int np = 0; np < 4; np++) {
                int nrow = np * 16 + (lane & 7) + ((lane >> 4) << 3);
                int ncol = ks * 16 + (((lane >> 3) & 1) << 3);
                uint32_t r0, r1, r2, r3;
                ldm_x4(r0, r1, r2, r3, kbs + (uint32_t)((nrow * FLDS + ncol) * 2));
                bfr[2*np][0] = r0; bfr[2*np][1] = r1;
                bfr[2*np+1][0] = r2; bfr[2*np+1][1] = r3;
            }
            #pragma unroll
            for (int mt = 0; mt < 2; mt++)
                #pragma unroll
                for (int j = 0; j < 8; j++)
                    mma16816(sc[mt][j], qa[mt][ks][0], qa[mt][ks][1],
                             qa[mt][ks][2], qa[mt][ks][3], bfr[j][0], bfr[j][1]);
        }

        // ---- causal mask (only diagonal key tiles) ----
        if (kt >= 2 * qt) {
            #pragma unroll
            for (int mt = 0; mt < 2; mt++) {
                int row0 = qt * 128 + wm + mt * 16 + (lane >> 2);
                int colb = kt * 64 + 2 * (lane & 3);
                #pragma unroll
                for (int j = 0; j < 8; j++) {
                    #pragma unroll
                    for (int cc = 0; cc < 2; cc++) {
                        int col = colb + j * 8 + cc;
                        if (col > row0)     sc[mt][j][cc]     = -1e30f;
                        if (col > row0 + 8) sc[mt][j][2 + cc] = -1e30f;
                    }
                }
            }
        }

        // ---- online softmax + P packing ----
        uint32_t pa[2][4][4];
        float corr[2][2];
        #pragma unroll
        for (int mt = 0; mt < 2; mt++) {
            float mx0 = -1e30f, mx1 = -1e30f;
            #pragma unroll
            for (int j = 0; j < 8; j++) {
                mx0 = fmaxf(mx0, fmaxf(sc[mt][j][0], sc[mt][j][1]));
                mx1 = fmaxf(mx1, fmaxf(sc[mt][j][2], sc[mt][j][3]));
            }
            mx0 = fmaxf(mx0, __shfl_xor_sync(0xffffffffu, mx0, 1));
            mx0 = fmaxf(mx0, __shfl_xor_sync(0xffffffffu, mx0, 2));
            mx1 = fmaxf(mx1, __shfl_xor_sync(0xffffffffu, mx1, 1));
            mx1 = fmaxf(mx1, __shfl_xor_sync(0xffffffffu, mx1, 2));
            float nm0 = fmaxf(mrow[mt][0], mx0), nm1 = fmaxf(mrow[mt][1], mx1);
            corr[mt][0] = fexp2((mrow[mt][0] - nm0) * alpha);
            corr[mt][1] = fexp2((mrow[mt][1] - nm1) * alpha);
            mrow[mt][0] = nm0; mrow[mt][1] = nm1;
            float ma0 = nm0 * alpha, ma1 = nm1 * alpha;

            float rs0 = 0.f, rs1 = 0.f;
            #pragma unroll
            for (int j = 0; j < 8; j++) {
                float p0 = fexp2(fmaf(sc[mt][j][0], alpha, -ma0));
                float p1 = fexp2(fmaf(sc[mt][j][1], alpha, -ma0));
                float p2 = fexp2(fmaf(sc[mt][j][2], alpha, -ma1));
                float p3 = fexp2(fmaf(sc[mt][j][3], alpha, -ma1));
                rs0 += p0 + p1; rs1 += p2 + p3;
                int ks = j >> 1, hi = (j & 1) << 1;
                pa[mt][ks][hi]     = h2_as_u32(__floats2half2_rn(p0, p1));
                pa[mt][ks][hi + 1] = h2_as_u32(__floats2half2_rn(p2, p3));
            }
            rs0 += __shfl_xor_sync(0xffffffffu, rs0, 1);
            rs0 += __shfl_xor_sync(0xffffffffu, rs0, 2);
            rs1 += __shfl_xor_sync(0xffffffffu, rs1, 1);
            rs1 += __shfl_xor_sync(0xffffffffu, rs1, 2);
            lrow[mt][0] = lrow[mt][0] * corr[mt][0] + rs0;
            lrow[mt][1] = lrow[mt][1] * corr[mt][1] + rs1;
            #pragma unroll
            for (int j = 0; j < 8; j++) {
                oc[mt][j][0] *= corr[mt][0]; oc[mt][j][1] *= corr[mt][0];
                oc[mt][j][2] *= corr[mt][1]; oc[mt][j][3] *= corr[mt][1];
            }
        }

        // ---- O += P V ----
        uint32_t vbs = vb + (uint32_t)(kt & 1) * 64 * FLDS * 2;
        #pragma unroll
        for (int ks = 0; ks < 4; ks++) {
            uint32_t vfr[8][2];
            #pragma unroll
            for (int np = 0; np < 4; np++) {
                int nrow = np * 16 + (lane & 7) + ((lane >> 4) << 3);
                int ncol = ks * 16 + (((lane >> 3) & 1) << 3);
                uint32_t r0, r1, r2, r3;
                ldm_x4(r0, r1, r2, r3, vbs + (uint32_t)((nrow * FLDS + ncol) * 2));
                vfr[2*np][0] = r0; vfr[2*np][1] = r1;
                vfr[2*np+1][0] = r2; vfr[2*np+1][1] = r3;
            }
            #pragma unroll
            for (int mt = 0; mt < 2; mt++)
                #pragma unroll
                for (int j = 0; j < 8; j++)
                    mma16816(oc[mt][j], pa[mt][ks][0], pa[mt][ks][1],
                             pa[mt][ks][2], pa[mt][ks][3], vfr[j][0], vfr[j][1]);
        }
        __syncthreads();
    }

    // ---- write O (concat layout, fp16) ----
    #pragma unroll
    for (int mt = 0; mt < 2; mt++) {
        float i0 = 1.0f / lrow[mt][0], i1 = 1.0f / lrow[mt][1];
        int row0 = qt * 128 + wm + mt * 16 + (lane >> 2);
        size_t base0 = ((size_t)b * S_ + row0) * E_ + h * 64 + 2 * (lane & 3);
        size_t base1 = base0 + (size_t)8 * E_;
        #pragma unroll
        for (int j = 0; j < 8; j++) {
            *(__half2*)(O + base0 + j * 8) = __floats2half2_rn(oc[mt][j][0] * i0,
                                                               oc[mt][j][1] * i0);
            *(__half2*)(O + base1 + j * 8) = __floats2half2_rn(oc[mt][j][2] * i1,
                                                               oc[mt][j][3] * i1);
        }
    }
}

// ---------------- host launcher ----------------
extern "C" void kernel_launch(void* const* d_in, const int* in_sizes, int n_in,
                              void* d_out, int out_size)
{
    const float* x   = (const float*)d_in[0];
    const float* Wq  = (const float*)d_in[1];
    const float* Wk  = (const float*)d_in[2];
    const float* Wv  = (const float*)d_in[3];
    const float* Wo  = (const float*)d_in[4];
    const float* bo  = (const float*)d_in[5];
    const float* W1  = (const float*)d_in[6];
    const float* b1  = (const float*)d_in[7];
    const float* W2  = (const float*)d_in[8];
    const float* b2  = (const float*)d_in[9];
    const float* g1  = (const float*)d_in[10];
    const float* be1 = (const float*)d_in[11];
    const float* g2  = (const float*)d_in[12];
    const float* be2 = (const float*)d_in[13];
    float* out = (float*)d_out;

    void *nx, *wqkv, *wo, *w1, *w2, *q, *k, *vt, *attn, *x1, *nx2, *ffn;
    cudaGetSymbolAddress(&nx, g_nx);
    cudaGetSymbolAddress(&wqkv, g_wqkv);
    cudaGetSymbolAddress(&wo, g_wo);
    cudaGetSymbolAddress(&w1, g_w1);
    cudaGetSymbolAddress(&w2, g_w2);
    cudaGetSymbolAddress(&q, g_q); cudaGetSymbolAddress(&k, g_k);
    cudaGetSymbolAddress(&vt, g_vt);
    cudaGetSymbolAddress(&attn, g_attn);
    cudaGetSymbolAddress(&x1, g_x1);
    cudaGetSymbolAddress(&nx2, g_nx2);
    cudaGetSymbolAddress(&ffn, g_ffn);

    cudaFuncSetAttribute(gemm_mma_kernel<0>, cudaFuncAttributeMaxDynamicSharedMemorySize, GEMM_SMEM);
    cudaFuncSetAttribute(gemm_mma_kernel<1>, cudaFuncAttributeMaxDynamicSharedMemorySize, GEMM_SMEM);
    cudaFuncSetAttribute(gemm_mma_kernel<2>, cudaFuncAttributeMaxDynamicSharedMemorySize, GEMM_SMEM);
    cudaFuncSetAttribute(gemm_mma_kernel<3>, cudaFuncAttributeMaxDynamicSharedMemorySize, GEMM_SMEM);
    cudaFuncSetAttribute(flash_kernel, cudaFuncAttributeMaxDynamicSharedMemorySize, FLASH_SMEM);

    // 1. weight transpose -> fp16
    wqkv_fp16_kernel<<<dim3(E_/32, NQKV/32), 256>>>(Wq, Wk, Wv, (__half*)wqkv);
    wt_fp16_kernel<<<dim3(E_/32, E_/32), 256>>>(Wo, E_, E_, (__half*)wo);
    wt_fp16_kernel<<<dim3(E_/32, FF_/32), 256>>>(W1, E_, FF_, (__half*)w1);
    wt_fp16_kernel<<<dim3(FF_/32, E_/32), 256>>>(W2, FF_, E_, (__half*)w2);
    // 2. LN1 -> fp16
    ln_fp16_kernel<<<TOK, 256>>>(x, g1, be1, (__half*)nx);
    // 3. fused QKV GEMM (N=3072) -> q,k fp16 [B,H,S,DH]; v fp16 [B,H,DH,S]
    gemm_mma_kernel<0><<<dim3(NQKV/128, TOK/128), 128, GEMM_SMEM>>>(
        (__half*)nx, (__half*)wqkv, nullptr, nullptr, nullptr, nullptr,
        (__half*)q, (__half*)k, (__half*)vt, E_, 0);
    // 4. HMMA flash attention -> attn fp16
    flash_kernel<<<dim3(S_/128, H_, B_), 128, FLASH_SMEM>>>(
        (__half*)q, (__half*)k, (__half*)vt, (__half*)attn);
    // 5. output projection + residual -> x1 fp32
    gemm_mma_kernel<1><<<dim3(E_/128, TOK/128), 128, GEMM_SMEM>>>(
        (__half*)attn, (__half*)wo, bo, x,
        (float*)x1, nullptr, nullptr, nullptr, nullptr, E_, E_);
    // 6. LN2 -> fp16
    ln_fp16_kernel<<<TOK, 256>>>((float*)x1, g2, be2, (__half*)nx2);
    // 7. FFN1: relu(+b1) -> ffn fp16
    gemm_mma_kernel<2><<<dim3(FF_/128, TOK/128), 128, GEMM_SMEM>>>(
        (__half*)nx2, (__half*)w1, b1, nullptr,
        nullptr, (__half*)ffn, nullptr, nullptr, nullptr, E_, FF_);
    // 8. FFN2: +b2 +x1 -> out
    gemm_mma_kernel<3><<<dim3(E_/128, TOK/128), 128, GEMM_SMEM>>>(
        (__half*)ffn, (__half*)w2, b2, (float*)x1,
        out, nullptr, nullptr, nullptr, nullptr, FF_, E_);
}

// round 17
// speedup vs baseline: 1.0717x; 1.0090x over previous
#include <cuda_runtime.h>
#include <cuda_fp16.h>
#include <cstdint>

#define B_   2
#define S_   2048
#define E_   1024
#define H_   16
#define DH_  64
#define FF_  4096
#define TOK  (B_*S_)   // 4096
#define NQKV 3072

// ---------------- scratch (no allocs allowed) ----------------
__device__ __half g_nx   [TOK*(size_t)E_];
__device__ __half g_wqkv [(size_t)NQKV*E_];
__device__ __half g_wo   [(size_t)E_*E_];
__device__ __half g_w1   [(size_t)FF_*E_];
__device__ __half g_w2   [(size_t)E_*FF_];
__device__ __half g_q [(size_t)B_*H_*S_*DH_];
__device__ __half g_k [(size_t)B_*H_*S_*DH_];
__device__ __half g_vt[(size_t)B_*H_*DH_*S_];   // V transposed: [B,H,DH,S]
__device__ __half g_attn[TOK*(size_t)E_];
__device__ float g_x1[TOK*(size_t)E_];
__device__ __half g_nx2 [TOK*(size_t)E_];
__device__ __half g_ffn [TOK*(size_t)FF_];

// ---------------- PTX helpers (base-target-safe: sm_80 features) -------------
__device__ __forceinline__ uint32_t smem_u32(const void* p) {
    uint32_t a;
    asm("{ .reg .u64 t; cvta.to.shared.u64 t, %1; cvt.u32.u64 %0, t; }" : "=r"(a) : "l"(p));
    return a;
}
__device__ __forceinline__ uint32_t h2_as_u32(__half2 h) {
    union { __half2 h2; uint32_t u; } cvt;
    cvt.h2 = h;
    return cvt.u;
}
__device__ __forceinline__ void cp16(uint32_t s, const void* g) {
    asm volatile("cp.async.cg.shared.global [%0], [%1], 16;" :: "r"(s), "l"(g));
}
#define CP_COMMIT() asm volatile("cp.async.commit_group;" ::: "memory")
#define CP_WAIT(n)  asm volatile("cp.async.wait_group %0;" :: "n"(n) : "memory")

__device__ __forceinline__ void ldm_x4(uint32_t& r0, uint32_t& r1, uint32_t& r2,
                                       uint32_t& r3, uint32_t a) {
    asm volatile("ldmatrix.sync.aligned.m8n8.x4.shared.b16 {%0,%1,%2,%3}, [%4];"
                 : "=r"(r0), "=r"(r1), "=r"(r2), "=r"(r3) : "r"(a));
}
__device__ __forceinline__ void mma16816(float* c, uint32_t a0, uint32_t a1,
                                         uint32_t a2, uint32_t a3,
                                         uint32_t b0, uint32_t b1) {
    asm volatile(
        "mma.sync.aligned.m16n8k16.row.col.f32.f16.f16.f32 "
        "{%0,%1,%2,%3},{%4,%5,%6,%7},{%8,%9},{%0,%1,%2,%3};"
        : "+f"(c[0]), "+f"(c[1]), "+f"(c[2]), "+f"(c[3])
        : "r"(a0), "r"(a1), "r"(a2), "r"(a3), "r"(b0), "r"(b1));
}

// fast 2^x on the FMA pipe (no MUFU). x clamped to [-125, ~0]. rel err ~1e-7.
__device__ __forceinline__ float fexp2(float x) {
    x = fmaxf(x, -125.0f);
    float t = x + 12582912.0f;              // 1.5*2^23: round-to-int in mantissa
    int n = __float_as_int(t) - 0x4B400000; // integer part
    float f = x - (t - 12582912.0f);        // frac in [-0.5, 0.5]
    float p =              1.5403530e-4f;
    p = fmaf(p, f, 1.3333558e-3f);
    p = fmaf(p, f, 9.6181291e-3f);
    p = fmaf(p, f, 5.5504109e-2f);
    p = fmaf(p, f, 2.4022651e-1f);
    p = fmaf(p, f, 6.9314718e-1f);
    p = fmaf(p, f, 1.0f);
    return p * __int_as_float((n + 127) << 23);
}

// ---------------- fused prep: LN1 + all weight transposes, one launch --------
// blocks [0,3072): wqkv  (32 x 96)
// blocks [3072,4096): wo (32 x 32)
// blocks [4096,8192): w1 (32 x 128)
// blocks [8192,12288): w2 (128 x 32)
// blocks [12288,16384): LN1 (token = idx)
#define PREP_BLOCKS 16384

__device__ __forceinline__ void wt_body(
    const float* __restrict__ W, int K, int N, __half* __restrict__ o,
    int bx, int by, float (*t)[33])
{
    int k0 = bx * 32, n0 = by * 32;
    {
        int tx = threadIdx.x & 31, ty = threadIdx.x >> 5;
        #pragma unroll
        for (int r = 0; r < 4; r++)
            t[ty + 8*r][tx] = W[(size_t)(k0 + ty + 8*r) * N + n0 + tx];
    }
    __syncthreads();
    int txp = threadIdx.x & 15;
    int tyn = threadIdx.x >> 4;
    #pragma unroll
    for (int r = 0; r < 2; r++) {
        int nn = tyn + 16 * r;
        __half2 v = __floats2half2_rn(t[2*txp][nn], t[2*txp + 1][nn]);
        *(__half2*)(o + (size_t)(n0 + nn) * K + k0 + 2*txp) = v;
    }
}

__global__ void __launch_bounds__(256) prep_kernel(
    const float* __restrict__ x, const float* __restrict__ g1,
    const float* __restrict__ be1,
    const float* __restrict__ Wq, const float* __restrict__ Wk,
    const float* __restrict__ Wv, const float* __restrict__ Wo,
    const float* __restrict__ W1, const float* __restrict__ W2,
    __half* __restrict__ nx, __half* __restrict__ wqkv,
    __half* __restrict__ wo, __half* __restrict__ w1, __half* __restrict__ w2)
{
    __shared__ float t[32][33];
    __shared__ float sh1[8], sh2[8];
    const int bid = blockIdx.x;
    const int tid = threadIdx.x;

    if (bid < 3072) {
        // ---- wqkv transpose: [H,E,DH]x3 -> Wt[3072,E] ----
        int bx = bid & 31, by = bid >> 5;
        int e0 = bx * 32, n0 = by * 32;
        const float* Wm = (n0 < 1024) ? Wq : (n0 < 2048) ? Wk : Wv;
        int nn0 = n0 & 1023;
        int h = nn0 >> 6, d0 = nn0 & 63;
        {
            int tx = tid & 31, ty = tid >> 5;
            #pragma unroll
            for (int r = 0; r < 4; r++)
                t[ty + 8*r][tx] = Wm[((size_t)h * E_ + e0 + ty + 8*r) * DH_ + d0 + tx];
        }
        __syncthreads();
        int txp = tid & 15, tyn = tid >> 4;
        #pragma unroll
        for (int r = 0; r < 2; r++) {
            int nn = tyn + 16 * r;
            __half2 v = __floats2half2_rn(t[2*txp][nn], t[2*txp + 1][nn]);
            *(__half2*)(wqkv + (size_t)(n0 + nn) * E_ + e0 + 2*txp) = v;
        }
    } else if (bid < 4096) {
        int i = bid - 3072;
        wt_body(Wo, E_, E_, wo, i & 31, i >> 5, t);
    } else if (bid < 8192) {
        int i = bid - 4096;
        wt_body(W1, E_, FF_, w1, i & 31, i >> 5, t);
    } else if (bid < 12288) {
        int i = bid - 8192;
        wt_body(W2, FF_, E_, w2, i & 127, i >> 7, t);
    } else {
        // ---- LN1 -> fp16 ----
        int tok = bid - 12288;
        const float4* xr = (const float4*)(x + (size_t)tok * E_);
        float4 v = xr[tid];
        float sum = v.x + v.y + v.z + v.w;
        float sq  = v.x*v.x + v.y*v.y + v.z*v.z + v.w*v.w;
        #pragma unroll
        for (int o2 = 16; o2 > 0; o2 >>= 1) {
            sum += __shfl_xor_sync(0xffffffffu, sum, o2);
            sq  += __shfl_xor_sync(0xffffffffu, sq,  o2);
        }
        if ((tid & 31) == 0) { sh1[tid >> 5] = sum; sh2[tid >> 5] = sq; }
        __syncthreads();
        if (tid < 32) {
            sum = (tid < 8) ? sh1[tid] : 0.f;
            sq  = (tid < 8) ? sh2[tid] : 0.f;
            #pragma unroll
            for (int o2 = 4; o2 > 0; o2 >>= 1) {
                sum += __shfl_xor_sync(0xffffffffu, sum, o2);
                sq  += __shfl_xor_sync(0xffffffffu, sq,  o2);
            }
            if (tid == 0) { sh1[0] = sum; sh2[0] = sq; }
        }
        __syncthreads();
        sum = sh1[0]; sq = sh2[0];
        float mu  = sum * (1.0f / E_);
        float var = sq * (1.0f / E_) - mu * mu;
        float rs  = rsqrtf(var + 1e-5f);
        float4 gv = ((const float4*)g1)[tid];
        float4 bv = ((const float4*)be1)[tid];
        float a0 = (v.x - mu) * rs * gv.x + bv.x;
        float a1 = (v.y - mu) * rs * gv.y + bv.y;
        float a2 = (v.z - mu) * rs * gv.z + bv.z;
        float a3 = (v.w - mu) * rs * gv.w + bv.w;
        size_t base = (size_t)tok * E_ + tid * 4;
        *(__half2*)(nx + base)     = __floats2half2_rn(a0, a1);
        *(__half2*)(nx + base + 2) = __floats2half2_rn(a2, a3);
    }
}

// ---------------- LayerNorm -> fp16: one block per token (LN2) ---------------
__global__ void __launch_bounds__(256) ln_fp16_kernel(
    const float* __restrict__ x, const float* __restrict__ g,
    const float* __restrict__ bta, __half* __restrict__ o)
{
    __shared__ float sh1[8], sh2[8];
    int tok = blockIdx.x;
    int t = threadIdx.x;
    const float4* xr = (const float4*)(x + (size_t)tok * E_);
    float4 v = xr[t];
    float sum = v.x + v.y + v.z + v.w;
    float sq  = v.x*v.x + v.y*v.y + v.z*v.z + v.w*v.w;
    #pragma unroll
    for (int o2 = 16; o2 > 0; o2 >>= 1) {
        sum += __shfl_xor_sync(0xffffffffu, sum, o2);
        sq  += __shfl_xor_sync(0xffffffffu, sq,  o2);
    }
    if ((t & 31) == 0) { sh1[t >> 5] = sum; sh2[t >> 5] = sq; }
    __syncthreads();
    if (t < 32) {
        sum = (t < 8) ? sh1[t] : 0.f;
        sq  = (t < 8) ? sh2[t] : 0.f;
        #pragma unroll
        for (int o2 = 4; o2 > 0; o2 >>= 1) {
            sum += __shfl_xor_sync(0xffffffffu, sum, o2);
            sq  += __shfl_xor_sync(0xffffffffu, sq,  o2);
        }
        if (t == 0) { sh1[0] = sum; sh2[0] = sq; }
    }
    __syncthreads();
    sum = sh1[0]; sq = sh2[0];
    float mu  = sum * (1.0f / E_);
    float var = sq * (1.0f / E_) - mu * mu;
    float rs  = rsqrtf(var + 1e-5f);
    float4 gv = ((const float4*)g)[t];
    float4 bv = ((const float4*)bta)[t];
    float a0 = (v.x - mu) * rs * gv.x + bv.x;
    float a1 = (v.y - mu) * rs * gv.y + bv.y;
    float a2 = (v.z - mu) * rs * gv.z + bv.z;
    float a3 = (v.w - mu) * rs * gv.w + bv.w;
    size_t base = (size_t)tok * E_ + t * 4;
    *(__half2*)(o + base)     = __floats2half2_rn(a0, a1);
    *(__half2*)(o + base + 2) = __floats2half2_rn(a2, a3);
}

// ---------------- HMMA GEMM: C[M,N] = A[M,K]*Bt[N,K]^T, plain fp16 -----------
// 128 threads, 4 warps, each warp 64x64. BK=32, 4 stages, distance-3 (R10).
#define BK     32
#define LDS    40
#define AELEMS (128 * LDS)
#define ABYTES (AELEMS * 2)            // 10240
#define STG_BYTES (2 * ABYTES)
#define GEMM_SMEM (4 * STG_BYTES)      // 81920 -> 2 CTA/SM
#define VSTG   136                     // V staging stride (halves)

template<int MODE>
__global__ void __launch_bounds__(128, 2) gemm_mma_kernel(
    const __half* __restrict__ A, const __half* __restrict__ Bt,
    const float* __restrict__ bias, const float* __restrict__ res,
    float* __restrict__ o0, __half* __restrict__ oh,
    __half* __restrict__ q16, __half* __restrict__ k16, __half* __restrict__ v16,
    int K, int ldC)
{
    extern __shared__ __half smbuf[];
    const uint32_t sbase = smem_u32(smbuf);
    const int NIT = K / BK;
    const int t = threadIdx.x;
    const int wid = t >> 5, lane = t & 31;
    const int bm = blockIdx.y * 128, bn = blockIdx.x * 128;
    const int wm = (wid & 1) * 64, wn = (wid >> 1) * 64;

    const __half* Abase = A  + (size_t)bm * K;
    const __half* Bbase = Bt + (size_t)bn * K;

    auto load_stage = [&](int st, int i) {
        uint32_t sa = sbase + st * STG_BYTES;
        int kc = i * BK;
        #pragma unroll
        for (int p = 0; p < 4; p++) {
            int idx = t + p * 128;
            int row = idx >> 2, ch = idx & 3;
            uint32_t off = (uint32_t)(row * LDS + ch * 8) * 2;
            cp16(sa + off,          Abase + (size_t)row * K + kc + ch * 8);
            cp16(sa + ABYTES + off, Bbase + (size_t)row * K + kc + ch * 8);
        }
    };

    #pragma unroll
    for (int s = 0; s < 3; s++) { load_stage(s, s); CP_COMMIT(); }

    float c[4][8][4];
    #pragma unroll
    for (int mt = 0; mt < 4; mt++)
        #pragma unroll
        for (int nt = 0; nt < 8; nt++)
            #pragma unroll
            for (int e = 0; e < 4; e++) c[mt][nt][e] = 0.f;

    for (int i = 0; i < NIT; i++) {
        CP_WAIT(2);
        __syncthreads();
        if (i + 3 < NIT) load_stage((i + 3) & 3, i + 3);
        CP_COMMIT();

        uint32_t sa = sbase + (i & 3) * STG_BYTES;
        uint32_t sb = sa + ABYTES;
        #pragma unroll
        for (int ks = 0; ks < 2; ks++) {
            uint32_t a[4][4];
            #pragma unroll
            for (int mt = 0; mt < 4; mt++) {
                uint32_t addr = sa + (uint32_t)(((wm + mt*16 + (lane & 15)) * LDS
                                  + ks*16 + (lane >> 4) * 8) * 2);
                ldm_x4(a[mt][0], a[mt][1], a[mt][2], a[mt][3], addr);
            }
            uint32_t b[8][2];
            #pragma unroll
            for (int np = 0; np < 4; np++) {
                int nrow = wn + np*16 + (lane & 7) + ((lane >> 4) << 3);
                int ncol = ks*16 + (((lane >> 3) & 1) << 3);
                uint32_t addr = sb + (uint32_t)((nrow * LDS + ncol) * 2);
                uint32_t r0, r1, r2, r3;
                ldm_x4(r0, r1, r2, r3, addr);
                b[2*np][0] = r0; b[2*np][1] = r1;
                b[2*np+1][0] = r2; b[2*np+1][1] = r3;
            }
            #pragma unroll
            for (int mt = 0; mt < 4; mt++)
                #pragma unroll
                for (int nt = 0; nt < 8; nt++)
                    mma16816(c[mt][nt], a[mt][0], a[mt][1], a[mt][2], a[mt][3],
                             b[nt][0], b[nt][1]);
        }
    }

    // ---------------- epilogue ----------------
    const int r = lane >> 2, cq = (lane & 3) * 2;

    if (MODE == 0 && bn >= 2048) {
        // ---- V tile: stage transposed in smem, then coalesced writeout ----
        __syncthreads();
        #pragma unroll
        for (int mt = 0; mt < 4; mt++) {
            #pragma unroll
            for (int half_ = 0; half_ < 2; half_++) {
                int ml = wm + mt * 16 + r + half_ * 8;
                #pragma unroll
                for (int nt = 0; nt < 8; nt++) {
                    int nl = wn + nt * 8 + cq;
                    smbuf[(nl)     * VSTG + ml] = __float2half_rn(c[mt][nt][half_ * 2 + 0]);
                    smbuf[(nl + 1) * VSTG + ml] = __float2half_rn(c[mt][nt][half_ * 2 + 1]);
                }
            }
        }
        __syncthreads();
        const int bb = bm >> 11;
        const int srow0 = bm & (S_ - 1);
        const int hh_base = (bn & 1023) >> 6;
        #pragma unroll
        for (int p = 0; p < 16; p++) {
            int ci  = t + p * 128;
            int row = ci >> 4;
            int ch  = ci & 15;
            int hh  = hh_base + (row >> 6);
            int d   = row & 63;
            uint4 val = *(uint4*)(smbuf + row * VSTG + ch * 8);
            *(uint4*)(v16 + ((size_t)(bb * H_ + hh) * DH_ + d) * S_ + srow0 + ch * 8) = val;
        }
        return;
    }

    #pragma unroll
    for (int mt = 0; mt < 4; mt++) {
        #pragma unroll
        for (int half_ = 0; half_ < 2; half_++) {
            int m = bm + wm + mt * 16 + r + half_ * 8;
            #pragma unroll
            for (int nt = 0; nt < 8; nt++) {
                int n = bn + wn + nt * 8 + cq;
                float v0 = c[mt][nt][half_ * 2 + 0];
                float v1 = c[mt][nt][half_ * 2 + 1];
                if (MODE == 0) {
                    int mat = n >> 10;
                    int hh = (n & 1023) >> 6, d = n & 63;
                    int bb = m >> 11, srow = m & (S_ - 1);
                    __half* dst = (mat == 0) ? q16 : k16;
                    *(__half2*)(dst + (((size_t)(bb * H_ + hh) * S_ + srow) << 6) + d)
                        = __floats2half2_rn(v0, v1);
                } else if (MODE == 2) {
                    float2 bv = *(const float2*)(bias + n);
                    v0 = fmaxf(v0 + bv.x, 0.f);
                    v1 = fmaxf(v1 + bv.y, 0.f);
                    *(__half2*)(oh + (size_t)m * ldC + n) = __floats2half2_rn(v0, v1);
                } else {
                    size_t base = (size_t)m * ldC + n;
                    float2 bv = *(const float2*)(bias + n);
                    float2 rv = *(const float2*)(res + base);
                    *(float2*)(o0 + base) = make_float2(v0 + bv.x + rv.x,
                                                        v1 + bv.y + rv.y);
                }
            }
        }
    }
}

// ---------------- HMMA flash attention (causal) -------------------------------
// 128 queries x 64 keys per tile, 4 warps (32 q-rows each), fp16 in, fp16 out.
#define FLDS 72
#define FLASH_SMEM ((128 + 4*64) * FLDS * 2)   // 55296 B

__global__ void __launch_bounds__(128, 2) flash_kernel(
    const __half* __restrict__ Q, const __half* __restrict__ Kp,
    const __half* __restrict__ Vt, __half* __restrict__ O)
{
    extern __shared__ __half fsm[];
    const uint32_t qb = smem_u32(fsm);                 // Q [128][72]
    const uint32_t kb = qb + 128 * FLDS * 2;           // K [2][64][72]
    const uint32_t vb = kb + 2 * 64 * FLDS * 2;        // Vt [2][64][72]

    const int qt = (int)gridDim.x - 1 - (int)blockIdx.x;   // heavy tiles first
    const int h = blockIdx.y, b = blockIdx.z;
    const int t = threadIdx.x, wid = t >> 5, lane = t & 31;
    const int wm = wid * 32;

    const __half* Qg = Q  + (((size_t)(b * H_ + h)) * S_ + qt * 128) * DH_;
    const __half* Kg = Kp + ((size_t)(b * H_ + h)) * S_ * DH_;
    const __half* Vg = Vt + ((size_t)(b * H_ + h)) * DH_ * S_;

    auto load_kv = [&](int kt) {
        uint32_t st = (uint32_t)(kt & 1) * 64 * FLDS * 2;
        #pragma unroll
        for (int p = 0; p < 4; p++) {
            int idx = t + p * 128;
            int row = idx >> 3, ch = idx & 7;
            uint32_t off = (uint32_t)(row * FLDS + ch * 8) * 2;
            cp16(kb + st + off, Kg + (size_t)(kt * 64 + row) * DH_ + ch * 8);
            cp16(vb + st + off, Vg + (size_t)row * S_ + kt * 64 + ch * 8);
        }
    };

    // Q + KV(0) in one group
    #pragma unroll
    for (int p = 0; p < 8; p++) {
        int idx = t + p * 128;
        int row = idx >> 3, ch = idx & 7;
        cp16(qb + (uint32_t)(row * FLDS + ch * 8) * 2, Qg + (size_t)row * DH_ + ch * 8);
    }
    load_kv(0);
    CP_COMMIT();

    const float alpha = 0.125f * 1.44269504f;   // scale * log2(e)
    float mrow[2][2], lrow[2][2];
    #pragma unroll
    for (int mt = 0; mt < 2; mt++) {
        mrow[mt][0] = -1e30f; mrow[mt][1] = -1e30f;
        lrow[mt][0] = 0.f;    lrow[mt][1] = 0.f;
    }
    float oc[2][8][4];
    #pragma unroll
    for (int mt = 0; mt < 2; mt++)
        #pragma unroll
        for (int j = 0; j < 8; j++)
            #pragma unroll
            for (int e = 0; e < 4; e++) oc[mt][j][e] = 0.f;

    uint32_t qa[2][4][4];
    const int nkt = 2 * qt + 2;

    for (int kt = 0; kt < nkt; kt++) {
        if (kt + 1 < nkt) { load_kv(kt + 1); CP_COMMIT(); CP_WAIT(1); }
        else              { CP_WAIT(0); }
        __syncthreads();

        if (kt == 0) {   // Q fragments, loaded once
            #pragma unroll
            for (int mt = 0; mt < 2; mt++)
                #pragma unroll
                for (int ks = 0; ks < 4; ks++) {
                    uint32_t addr = qb + (uint32_t)(((wm + mt*16 + (lane & 15)) * FLDS
                                       + ks * 16 + (lane >> 4) * 8) * 2);
                    ldm_x4(qa[mt][ks][0], qa[mt][ks][1], qa[mt][ks][2], qa[mt][ks][3], addr);
                }
        }

        // ---- S = Q K^T ----
        float sc[2][8][4];
        #pragma unroll
        for (int mt = 0; mt < 2; mt++)
            #pragma unroll
            for (int j = 0; j < 8; j++)
                #pragma unroll
                for (int e = 0; e < 4; e++) sc[mt][j][e] = 0.f;

        uint32_t kbs = kb + (uint32_t)(kt & 1) * 64 * FLDS * 2;
        #pragma unroll
        for (int ks = 0; ks < 4; ks++) {
            uint32_t bfr[8][2];
            #pragma unroll
            for (int np = 0; np < 4; np++) {
                int nrow = np * 16 + (lane & 7) + ((lane >> 4) << 3);
                int ncol = ks * 16 + (((lane >> 3) & 1) << 3);
                uint32_t r0, r1, r2, r3;
                ldm_x4(r0, r1, r2, r3, kbs + (uint32_t)((nrow * FLDS + ncol) * 2));
                bfr[2*np][0] = r0; bfr[2*np][1] = r1;
                bfr[2*np+1][0] = r2; bfr[2*np+1][1] = r3;
            }
            #pragma unroll
            for (int mt = 0; mt < 2; mt++)
                #pragma unroll
                for (int j = 0; j < 8; j++)
                    mma16816(sc[mt][j], qa[mt][ks][0], qa[mt][ks][1],
                             qa[mt][ks][2], qa[mt][ks][3], bfr[j][0], bfr[j][1]);
        }

        // ---- causal mask (only diagonal key tiles) ----
        if (kt >= 2 * qt) {
            #pragma unroll
            for (int mt = 0; mt < 2; mt++) {
                int row0 = qt * 128 + wm + mt * 16 + (lane >> 2);
                int colb = kt * 64 + 2 * (lane & 3);
                #pragma unroll
                for (int j = 0; j < 8; j++) {
                    #pragma unroll
                    for (int cc = 0; cc < 2; cc++) {
                        int col = colb + j * 8 + cc;
                        if (col > row0)     sc[mt][j][cc]     = -1e30f;
                        if (col > row0 + 8) sc[mt][j][2 + cc] = -1e30f;
                    }
                }
            }
        }

        // ---- online softmax + P packing ----
        uint32_t pa[2][4][4];
        float corr[2][2];
        #pragma unroll
        for (int mt = 0; mt < 2; mt++) {
            float mx0 = -1e30f, mx1 = -1e30f;
            #pragma unroll
            for (int j = 0; j < 8; j++) {
                mx0 = fmaxf(mx0, fmaxf(sc[mt][j][0], sc[mt][j][1]));
                mx1 = fmaxf(mx1, fmaxf(sc[mt][j][2], sc[mt][j][3]));
            }
            mx0 = fmaxf(mx0, __shfl_xor_sync(0xffffffffu, mx0, 1));
            mx0 = fmaxf(mx0, __shfl_xor_sync(0xffffffffu, mx0, 2));
            mx1 = fmaxf(mx1, __shfl_xor_sync(0xffffffffu, mx1, 1));
            mx1 = fmaxf(mx1, __shfl_xor_sync(0xffffffffu, mx1, 2));
            float nm0 = fmaxf(mrow[mt][0], mx0), nm1 = fmaxf(mrow[mt][1], mx1);
            corr[mt][0] = fexp2((mrow[mt][0] - nm0) * alpha);
            corr[mt][1] = fexp2((mrow[mt][1] - nm1) * alpha);
            mrow[mt][0] = nm0; mrow[mt][1] = nm1;
            float ma0 = nm0 * alpha, ma1 = nm1 * alpha;

            float rs0 = 0.f, rs1 = 0.f;
            #pragma unroll
            for (int j = 0; j < 8; j++) {
                float p0 = fexp2(fmaf(sc[mt][j][0], alpha, -ma0));
                float p1 = fexp2(fmaf(sc[mt][j][1], alpha, -ma0));
                float p2 = fexp2(fmaf(sc[mt][j][2], alpha, -ma1));
                float p3 = fexp2(fmaf(sc[mt][j][3], alpha, -ma1));
                rs0 += p0 + p1; rs1 += p2 + p3;
                int ks = j >> 1, hi = (j & 1) << 1;
                pa[mt][ks][hi]     = h2_as_u32(__floats2half2_rn(p0, p1));
                pa[mt][ks][hi + 1] = h2_as_u32(__floats2half2_rn(p2, p3));
            }
            rs0 += __shfl_xor_sync(0xffffffffu, rs0, 1);
            rs0 += __shfl_xor_sync(0xffffffffu, rs0, 2);
            rs1 += __shfl_xor_sync(0xffffffffu, rs1, 1);
            rs1 += __shfl_xor_sync(0xffffffffu, rs1, 2);
            lrow[mt][0] = lrow[mt][0] * corr[mt][0] + rs0;
            lrow[mt][1] = lrow[mt][1] * corr[mt][1] + rs1;
            #pragma unroll
            for (int j = 0; j < 8; j++) {
                oc[mt][j][0] *= corr[mt][0]; oc[mt][j][1] *= corr[mt][0];
                oc[mt][j][2] *= corr[mt][1]; oc[mt][j][3] *= corr[mt][1];
            }
        }

        // ---- O += P V ----
        uint32_t vbs = vb + (uint32_t)(kt & 1) * 64 * FLDS * 2;
        #pragma unroll
        for (int ks = 0; ks < 4; ks++) {
            uint32_t vfr[8][2];
            #pragma unroll
            for (int np = 0; np < 4; np++) {
                int nrow = np * 16 + (lane & 7) + ((lane >> 4) << 3);
                int ncol = ks * 16 + (((lane >> 3) & 1) << 3);
                uint32_t r0, r1, r2, r3;
                ldm_x4(r0, r1, r2, r3, vbs + (uint32_t)((nrow * FLDS + ncol) * 2));
                vfr[2*np][0] = r0; vfr[2*np][1] = r1;
                vfr[2*np+1][0] = r2; vfr[2*np+1][1] = r3;
            }
            #pragma unroll
            for (int mt = 0; mt < 2; mt++)
                #pragma unroll
                for (int j = 0; j < 8; j++)
                    mma16816(oc[mt][j], pa[mt][ks][0], pa[mt][ks][1],
                             pa[mt][ks][2], pa[mt][ks][3], vfr[j][0], vfr[j][1]);
        }
        __syncthreads();
    }

    // ---- write O (concat layout, fp16) ----
    #pragma unroll
    for (int mt = 0; mt < 2; mt++) {
        float i0 = 1.0f / lrow[mt][0], i1 = 1.0f / lrow[mt][1];
        int row0 = qt * 128 + wm + mt * 16 + (lane >> 2);
        size_t base0 = ((size_t)b * S_ + row0) * E_ + h * 64 + 2 * (lane & 3);
        size_t base1 = base0 + (size_t)8 * E_;
        #pragma unroll
        for (int j = 0; j < 8; j++) {
            *(__half2*)(O + base0 + j * 8) = __floats2half2_rn(oc[mt][j][0] * i0,
                                                               oc[mt][j][1] * i0);
            *(__half2*)(O + base1 + j * 8) = __floats2half2_rn(oc[mt][j][2] * i1,
                                                               oc[mt][j][3] * i1);
        }
    }
}

// ---------------- host launcher ----------------
extern "C" void kernel_launch(void* const* d_in, const int* in_sizes, int n_in,
                              void* d_out, int out_size)
{
    const float* x   = (const float*)d_in[0];
    const float* Wq  = (const float*)d_in[1];
    const float* Wk  = (const float*)d_in[2];
    const float* Wv  = (const float*)d_in[3];
    const float* Wo  = (const float*)d_in[4];
    const float* bo  = (const float*)d_in[5];
    const float* W1  = (const float*)d_in[6];
    const float* b1  = (const float*)d_in[7];
    const float* W2  = (const float*)d_in[8];
    const float* b2  = (const float*)d_in[9];
    const float* g1  = (const float*)d_in[10];
    const float* be1 = (const float*)d_in[11];
    const float* g2  = (const float*)d_in[12];
    const float* be2 = (const float*)d_in[13];
    float* out = (float*)d_out;

    void *nx, *wqkv, *wo, *w1, *w2, *q, *k, *vt, *attn, *x1, *nx2, *ffn;
    cudaGetSymbolAddress(&nx, g_nx);
    cudaGetSymbolAddress(&wqkv, g_wqkv);
    cudaGetSymbolAddress(&wo, g_wo);
    cudaGetSymbolAddress(&w1, g_w1);
    cudaGetSymbolAddress(&w2, g_w2);
    cudaGetSymbolAddress(&q, g_q); cudaGetSymbolAddress(&k, g_k);
    cudaGetSymbolAddress(&vt, g_vt);
    cudaGetSymbolAddress(&attn, g_attn);
    cudaGetSymbolAddress(&x1, g_x1);
    cudaGetSymbolAddress(&nx2, g_nx2);
    cudaGetSymbolAddress(&ffn, g_ffn);

    cudaFuncSetAttribute(gemm_mma_kernel<0>, cudaFuncAttributeMaxDynamicSharedMemorySize, GEMM_SMEM);
    cudaFuncSetAttribute(gemm_mma_kernel<1>, cudaFuncAttributeMaxDynamicSharedMemorySize, GEMM_SMEM);
    cudaFuncSetAttribute(gemm_mma_kernel<2>, cudaFuncAttributeMaxDynamicSharedMemorySize, GEMM_SMEM);
    cudaFuncSetAttribute(gemm_mma_kernel<3>, cudaFuncAttributeMaxDynamicSharedMemorySize, GEMM_SMEM);
    cudaFuncSetAttribute(flash_kernel, cudaFuncAttributeMaxDynamicSharedMemorySize, FLASH_SMEM);

    // 1. fused prep: LN1 + all weight transposes (one launch)
    prep_kernel<<<PREP_BLOCKS, 256>>>(x, g1, be1, Wq, Wk, Wv, Wo, W1, W2,
        (__half*)nx, (__half*)wqkv, (__half*)wo, (__half*)w1, (__half*)w2);
    // 2. fused QKV GEMM (N=3072) -> q,k fp16 [B,H,S,DH]; v fp16 [B,H,DH,S]
    gemm_mma_kernel<0><<<dim3(NQKV/128, TOK/128), 128, GEMM_SMEM>>>(
        (__half*)nx, (__half*)wqkv, nullptr, nullptr, nullptr, nullptr,
        (__half*)q, (__half*)k, (__half*)vt, E_, 0);
    // 3. HMMA flash attention -> attn fp16
    flash_kernel<<<dim3(S_/128, H_, B_), 128, FLASH_SMEM>>>(
        (__half*)q, (__half*)k, (__half*)vt, (__half*)attn);
    // 4. output projection + residual -> x1 fp32
    gemm_mma_kernel<1><<<dim3(E_/128, TOK/128), 128, GEMM_SMEM>>>(
        (__half*)attn, (__half*)wo, bo, x,
        (float*)x1, nullptr, nullptr, nullptr, nullptr, E_, E_);
    // 5. LN2 -> fp16
    ln_fp16_kernel<<<TOK, 256>>>((float*)x1, g2, be2, (__half*)nx2);
    // 6. FFN1: relu(+b1) -> ffn fp16
    gemm_mma_kernel<2><<<dim3(FF_/128, TOK/128), 128, GEMM_SMEM>>>(
        (__half*)nx2, (__half*)w1, b1, nullptr,
        nullptr, (__half*)ffn, nullptr, nullptr, nullptr, E_, FF_);
    // 7. FFN2: +b2 +x1 -> out
    gemm_mma_kernel<3><<<dim3(E_/128, TOK/128), 128, GEMM_SMEM>>>(
        (__half*)ffn, (__half*)w2, b2, (float*)x1,
        out, nullptr, nullptr, nullptr, nullptr, FF_, E_);
}